// round 9
// baseline (speedup 1.0000x reference)
#include <cuda_runtime.h>
#include <cuda_bf16.h>
#include <cstdint>

// LocalAttention2D: windowed MHSA. GEMMs on mma.sync bf16 (hi/lo split, 3-term,
// fp32 accumulate), attention in fp32 SIMT. One window (64 tokens) per CTA,
// 512 threads (16 warps) for latency hiding. Weights pre-packed to fragment
// layout in global memory (L2-resident, shared by all CTAs).

#define NWIN 4608

// ---- SMEM byte layout ----
#define XP_B     0        // X A-frag pack: [2 plane][4 mt][16 kt][32 lane][16B] = 65536
#define OP_B     65536    // O A-frag pack: [2 plane][4 mt][2 kt][32][16B] = 8192
#define SQT_B    73728    // [32][64] f32
#define SKT_B    81920    // [32][64] f32
#define SV_B     90112    // [64][34] f32 = 8704
#define SS_B     98816    // [64][68] f32 = 17408 (S, then aliased P^T)
#define SBIAS_B  116224   // 96 f32
#define SBIASP_B 116608   // 256 f32
#define SMEM_TOTAL 117632

// ---- global packed weight buffers (B-fragment layout, bf16 hi/lo planes) ----
__device__ uint2 gW1h[8 * 12 * 16 * 32];
__device__ uint2 gW1l[8 * 12 * 16 * 32];
__device__ uint2 gW2h[8 * 32 * 2 * 32];
__device__ uint2 gW2l[8 * 32 * 2 * 32];

__device__ __forceinline__ void mma16816(float* d, const uint4 a, const uint2 b) {
    asm volatile(
        "mma.sync.aligned.m16n8k16.row.col.f32.bf16.bf16.f32 "
        "{%0,%1,%2,%3}, {%4,%5,%6,%7}, {%8,%9}, {%0,%1,%2,%3};\n"
        : "+f"(d[0]), "+f"(d[1]), "+f"(d[2]), "+f"(d[3])
        : "r"(a.x), "r"(a.y), "r"(a.z), "r"(a.w), "r"(b.x), "r"(b.y));
}

__device__ __forceinline__ void split2(float a, float b, uint32_t& hi, uint32_t& lo) {
    __nv_bfloat16 ha = __float2bfloat16(a), hb = __float2bfloat16(b);
    float ra = a - __bfloat162float(ha), rb = b - __bfloat162float(hb);
    __nv_bfloat16 la = __float2bfloat16(ra), lb = __float2bfloat16(rb);
    hi = (uint32_t)__bfloat16_as_ushort(ha) | ((uint32_t)__bfloat16_as_ushort(hb) << 16);
    lo = (uint32_t)__bfloat16_as_ushort(la) | ((uint32_t)__bfloat16_as_ushort(lb) << 16);
}

// ---------------- pre-pack kernels (unchanged, verified R8) ----------------
__global__ void pack_w1_kernel(const float* __restrict__ w_qkv) {
    const int gid = blockIdx.x * 256 + threadIdx.x;     // 0..49151
    const int lane = gid & 31;
    const int kt   = (gid >> 5) & 15;
    const int nt   = (gid >> 9) % 12;
    const int h    = (gid >> 9) / 12;
    const int c    = nt * 8 + (lane >> 2);
    const int grow = (c >> 5) * 256 + h * 32 + (c & 31);
    const int k0   = kt * 16 + (lane & 3) * 2;
    const float a0 = w_qkv[grow * 256 + k0],     a1 = w_qkv[grow * 256 + k0 + 1];
    const float b0 = w_qkv[grow * 256 + k0 + 8], b1 = w_qkv[grow * 256 + k0 + 9];
    uint32_t hx, lx, hy, ly;
    split2(a0, a1, hx, lx);
    split2(b0, b1, hy, ly);
    gW1h[gid] = make_uint2(hx, hy);
    gW1l[gid] = make_uint2(lx, ly);
}

__global__ void pack_w2_kernel(const float* __restrict__ w_proj) {
    const int gid = blockIdx.x * 256 + threadIdx.x;     // 0..16383
    const int lane = gid & 31;
    const int kt   = (gid >> 5) & 1;
    const int nt   = (gid >> 6) & 31;
    const int h    = gid >> 11;
    const int n    = nt * 8 + (lane >> 2);
    const int k    = h * 32 + kt * 16 + (lane & 3) * 2;
    const float a0 = w_proj[n * 256 + k],     a1 = w_proj[n * 256 + k + 1];
    const float b0 = w_proj[n * 256 + k + 8], b1 = w_proj[n * 256 + k + 9];
    uint32_t hx, lx, hy, ly;
    split2(a0, a1, hx, lx);
    split2(b0, b1, hy, ly);
    gW2h[gid] = make_uint2(hx, hy);
    gW2l[gid] = make_uint2(lx, ly);
}

__device__ __forceinline__ int row_gbase(int win, int tok) {
    const int b  = win / 576;
    const int wh = (win % 576) / 24;
    const int ww = win % 24;
    return ((b * 192 + wh * 8 + (tok >> 3)) * 192 + (ww * 8 + (tok & 7))) * 256;
}

__global__ __launch_bounds__(512, 1)
void win_mhsa_mma_kernel(const float* __restrict__ x,
                         const float* __restrict__ b_qkv,
                         const float* __restrict__ b_proj,
                         float* __restrict__ out)
{
    extern __shared__ char smc[];
    float* sQT    = (float*)(smc + SQT_B);
    float* sKT    = (float*)(smc + SKT_B);
    float* sV     = (float*)(smc + SV_B);
    float* sS     = (float*)(smc + SS_B);
    float* sBias  = (float*)(smc + SBIAS_B);
    float* sBiasP = (float*)(smc + SBIASP_B);

    const int tid  = threadIdx.x;
    const int wid  = tid >> 5;
    const int lane = tid & 31;
    const int win  = blockIdx.x;
    const float QSCALE = 0.17677669529663689f;   // 32^-0.5

    if (tid < 256) sBiasP[tid] = __ldg(&b_proj[tid]);

    // ---------------- X window -> A-fragment pack (hi/lo bf16) ----------------
    {
        const int row = tid >> 3, p = tid & 7;
        const float4* gx = reinterpret_cast<const float4*>(x + row_gbase(win, row));
        const int mt = row >> 4, rin = row & 15, g = rin & 7, rh = rin >> 3;
        #pragma unroll
        for (int u = 0; u < 8; u++) {
            const int k4 = p * 8 + u;
            const float4 v = __ldg(&gx[k4]);
            const int ktile = k4 >> 2;
            const int cpair = (k4 & 3) * 2;
            const float e[4] = { v.x, v.y, v.z, v.w };
            #pragma unroll
            for (int pr = 0; pr < 2; pr++) {
                const int cp = cpair + pr, c8 = cp >> 2, cc = cp & 3;
                const int laneX = g * 4 + cc, slot = rh + 2 * c8;
                uint32_t hi, lo;
                split2(e[pr * 2], e[pr * 2 + 1], hi, lo);
                char* base = smc + XP_B + (((mt * 16 + ktile) * 32 + laneX) << 4) + slot * 4;
                *reinterpret_cast<uint32_t*>(base)         = hi;
                *reinterpret_cast<uint32_t*>(base + 32768) = lo;
            }
        }
    }
    __syncthreads();

    const int mw = wid & 3;      // M-tile (16 tokens)
    const int nq = wid >> 2;     // N-quarter

    float acc2[8][4];
    #pragma unroll
    for (int i = 0; i < 8; i++)
        #pragma unroll
        for (int j = 0; j < 4; j++) acc2[i][j] = 0.0f;

    for (int h = 0; h < 8; h++) {
        if (tid < 96) sBias[tid] = __ldg(&b_qkv[(tid >> 5) * 256 + h * 32 + (tid & 31)]);

        // ============ GEMM1: QKV_h[64,96] = X[64,256] @ Wh^T ============
        float acc1[3][4];
        #pragma unroll
        for (int i = 0; i < 3; i++)
            #pragma unroll
            for (int j = 0; j < 4; j++) acc1[i][j] = 0.0f;

        {
            const uint2* w1h = gW1h + ((h * 12 + nq * 3) * 16) * 32 + lane;
            const uint2* w1l = gW1l + ((h * 12 + nq * 3) * 16) * 32 + lane;
            #pragma unroll 4
            for (int kt = 0; kt < 16; kt++) {
                const char* ab = smc + XP_B + (((mw * 16 + kt) * 32 + lane) << 4);
                const uint4 Ah = *reinterpret_cast<const uint4*>(ab);
                const uint4 Al = *reinterpret_cast<const uint4*>(ab + 32768);
                #pragma unroll
                for (int nt = 0; nt < 3; nt++) {
                    const uint2 Bh = __ldg(&w1h[(nt * 16 + kt) * 32]);
                    const uint2 Bl = __ldg(&w1l[(nt * 16 + kt) * 32]);
                    mma16816(acc1[nt], Ah, Bh);
                    mma16816(acc1[nt], Ah, Bl);
                    mma16816(acc1[nt], Al, Bh);
                }
            }
        }

        // scatter QKV (+bias) to attention layouts
        {
            const int g = lane >> 2, c = (lane & 3) * 2;
            #pragma unroll
            for (int nt = 0; nt < 3; nt++) {
                const int colb = (nq * 3 + nt) * 8 + c;
                #pragma unroll
                for (int e = 0; e < 4; e++) {
                    const int col = colb + (e & 1);
                    const int tok = mw * 16 + g + (e >> 1) * 8;
                    const float v = acc1[nt][e] + sBias[col];
                    if (col < 32)       sQT[col * 64 + tok] = v * QSCALE;
                    else if (col < 64)  sKT[(col - 32) * 64 + tok] = v;
                    else                sV[tok * 34 + (col - 64)] = v;
                }
            }
        }
        __syncthreads();

        // ============ attention (fp32 SIMT, 512 threads) ============
        const int tg = tid >> 4, cg = tid & 15;
        const int t0 = tg * 2, j0 = cg * 4, d0 = cg * 2;

        {   // S = Q K^T : 2x4 microtile
            float sacc[2][4];
            #pragma unroll
            for (int m = 0; m < 2; m++)
                #pragma unroll
                for (int n = 0; n < 4; n++) sacc[m][n] = 0.0f;
            #pragma unroll
            for (int d = 0; d < 32; d++) {
                const float2 qa = *reinterpret_cast<const float2*>(&sQT[d * 64 + t0]);
                const float4 kb = *reinterpret_cast<const float4*>(&sKT[d * 64 + j0]);
                const float qv[2] = { qa.x, qa.y };
                const float kv[4] = { kb.x, kb.y, kb.z, kb.w };
                #pragma unroll
                for (int m = 0; m < 2; m++)
                    #pragma unroll
                    for (int n = 0; n < 4; n++)
                        sacc[m][n] += qv[m] * kv[n];
            }
            #pragma unroll
            for (int m = 0; m < 2; m++)
                *reinterpret_cast<float4*>(&sS[(t0 + m) * 68 + j0]) =
                    make_float4(sacc[m][0], sacc[m][1], sacc[m][2], sacc[m][3]);
        }
        __syncthreads();

        {   // softmax rows (8 lanes/row) -> P^T (aliased buffer)
            const int r = tid >> 3, p = tid & 7;
            float v[8];
            const float* row = &sS[r * 68 + p * 8];
            #pragma unroll
            for (int u = 0; u < 2; u++) {
                const float4 f = *reinterpret_cast<const float4*>(row + u * 4);
                v[u * 4 + 0] = f.x; v[u * 4 + 1] = f.y;
                v[u * 4 + 2] = f.z; v[u * 4 + 3] = f.w;
            }
            float mx = v[0];
            #pragma unroll
            for (int i = 1; i < 8; i++) mx = fmaxf(mx, v[i]);
            mx = fmaxf(mx, __shfl_xor_sync(0xffffffffu, mx, 1));
            mx = fmaxf(mx, __shfl_xor_sync(0xffffffffu, mx, 2));
            mx = fmaxf(mx, __shfl_xor_sync(0xffffffffu, mx, 4));
            float sum = 0.0f;
            #pragma unroll
            for (int i = 0; i < 8; i++) { v[i] = __expf(v[i] - mx); sum += v[i]; }
            sum += __shfl_xor_sync(0xffffffffu, sum, 1);
            sum += __shfl_xor_sync(0xffffffffu, sum, 2);
            sum += __shfl_xor_sync(0xffffffffu, sum, 4);
            const float inv = 1.0f / sum;
            __syncthreads();   // all S reads done before aliased P^T writes
            #pragma unroll
            for (int i = 0; i < 8; i++) sS[(p * 8 + i) * 68 + r] = v[i] * inv;
        }
        __syncthreads();

        {   // O = P V -> OPack (A-frag hi/lo)
            float oacc[2][2];
            #pragma unroll
            for (int m = 0; m < 2; m++) { oacc[m][0] = 0.0f; oacc[m][1] = 0.0f; }
            #pragma unroll 8
            for (int j = 0; j < 64; j++) {
                const float2 pa = *reinterpret_cast<const float2*>(&sS[j * 68 + t0]);
                const float2 vb = *reinterpret_cast<const float2*>(&sV[j * 34 + d0]);
                oacc[0][0] += pa.x * vb.x;
                oacc[0][1] += pa.x * vb.y;
                oacc[1][0] += pa.y * vb.x;
                oacc[1][1] += pa.y * vb.y;
            }
            const int ktile = cg >> 3, cpr = cg & 7;
            const int c8 = cpr >> 2, cc = cpr & 3;
            #pragma unroll
            for (int m = 0; m < 2; m++) {
                const int r = t0 + m;
                const int mt = r >> 4, rin = r & 15, g = rin & 7, rh = rin >> 3;
                const int laneO = g * 4 + cc, slot = rh + 2 * c8;
                uint32_t hi, lo;
                split2(oacc[m][0], oacc[m][1], hi, lo);
                char* base = smc + OP_B + (((mt * 2 + ktile) * 32 + laneO) << 4) + slot * 4;
                *reinterpret_cast<uint32_t*>(base)        = hi;
                *reinterpret_cast<uint32_t*>(base + 4096) = lo;
            }
        }
        __syncthreads();

        // ============ GEMM2: Y += O_h @ Wproj_h^T (reg accumulate) ============
        {
            const uint2* w2h = gW2h + ((h * 32 + nq * 8) * 2) * 32 + lane;
            const uint2* w2l = gW2l + ((h * 32 + nq * 8) * 2) * 32 + lane;
            #pragma unroll
            for (int kt = 0; kt < 2; kt++) {
                const char* ab = smc + OP_B + (((mw * 2 + kt) * 32 + lane) << 4);
                const uint4 Ah = *reinterpret_cast<const uint4*>(ab);
                const uint4 Al = *reinterpret_cast<const uint4*>(ab + 4096);
                #pragma unroll
                for (int nt = 0; nt < 8; nt++) {
                    const uint2 Bh = __ldg(&w2h[(nt * 2 + kt) * 32]);
                    const uint2 Bl = __ldg(&w2l[(nt * 2 + kt) * 32]);
                    mma16816(acc2[nt], Ah, Bh);
                    mma16816(acc2[nt], Ah, Bl);
                    mma16816(acc2[nt], Al, Bh);
                }
            }
        }
        __syncthreads();   // OP free before next head's attention rewrites it
    } // heads

    // ---------------- epilogue: Y + b_proj -> global ----------------
    {
        const int g = lane >> 2, c = (lane & 3) * 2;
        const int tok0 = mw * 16 + g, tok1 = tok0 + 8;
        float* g0 = out + row_gbase(win, tok0);
        float* g1 = out + row_gbase(win, tok1);
        #pragma unroll
        for (int nt = 0; nt < 8; nt++) {
            const int colb = (nq * 8 + nt) * 8 + c;
            const float b0 = sBiasP[colb], b1 = sBiasP[colb + 1];
            float2 v0 = make_float2(acc2[nt][0] + b0, acc2[nt][1] + b1);
            float2 v1 = make_float2(acc2[nt][2] + b0, acc2[nt][3] + b1);
            *reinterpret_cast<float2*>(g0 + colb) = v0;
            *reinterpret_cast<float2*>(g1 + colb) = v1;
        }
    }
}

extern "C" void kernel_launch(void* const* d_in, const int* in_sizes, int n_in,
                              void* d_out, int out_size)
{
    const float* x      = (const float*)d_in[0];
    const float* w_qkv  = (const float*)d_in[1];
    const float* b_qkv  = (const float*)d_in[2];
    const float* w_proj = (const float*)d_in[3];
    const float* b_proj = (const float*)d_in[4];
    float* out = (float*)d_out;
    (void)in_sizes; (void)n_in; (void)out_size;

    pack_w1_kernel<<<192, 256>>>(w_qkv);
    pack_w2_kernel<<<64, 256>>>(w_proj);

    cudaFuncSetAttribute(win_mhsa_mma_kernel,
                         cudaFuncAttributeMaxDynamicSharedMemorySize, SMEM_TOTAL);
    win_mhsa_mma_kernel<<<NWIN, 512, SMEM_TOTAL>>>(x, b_qkv, b_proj, out);
}

// round 12
// speedup vs baseline: 1.1629x; 1.1629x over previous
#include <cuda_runtime.h>
#include <cuda_bf16.h>
#include <cstdint>

// LocalAttention2D: windowed MHSA. GEMMs on mma.sync bf16 (hi/lo split, 3-term,
// fp32 accumulate), attention in fp32 SIMT. One window per CTA, 256 threads.
// Heads processed in PAIRS per phase (2 independent chains per thread) to cut
// barrier count ~3x. Weights pre-packed to fragment layout in gmem (L2-resident).

#define NWIN 4608

// ---- SMEM byte layout ----
#define XP_B      0        // X A-frag pack: [2 plane][4 mt][16 kt][32 lane][16B] = 65536
#define OP0_B     65536    // O A-frag pack head0: 8192
#define OP1_B     73728    // O A-frag pack head1: 8192
#define SQT0_B    81920    // [32][64] f32
#define SQT1_B    90112
#define SKT0_B    98304
#define SKT1_B    106496
#define SV0_B     114688   // [64][34] f32 = 8704
#define SV1_B     123392
#define SS0_B     132096   // [64][68] f32 = 17408
#define SS1_B     149504
#define SP0_B     166912   // [64][68] f32 (P^T)
#define SP1_B     184320
#define SBIASQ_B  201728   // 768 f32 (all b_qkv) = 3072
#define SBIASP_B  204800   // 256 f32 = 1024
#define SMEM_TOTAL 205824

// ---- global packed weight buffers (B-fragment layout, bf16 hi/lo planes) ----
__device__ uint2 gW1h[8 * 12 * 16 * 32];
__device__ uint2 gW1l[8 * 12 * 16 * 32];
__device__ uint2 gW2h[8 * 32 * 2 * 32];
__device__ uint2 gW2l[8 * 32 * 2 * 32];

__device__ __forceinline__ void mma16816(float* d, const uint4 a, const uint2 b) {
    asm volatile(
        "mma.sync.aligned.m16n8k16.row.col.f32.bf16.bf16.f32 "
        "{%0,%1,%2,%3}, {%4,%5,%6,%7}, {%8,%9}, {%0,%1,%2,%3};\n"
        : "+f"(d[0]), "+f"(d[1]), "+f"(d[2]), "+f"(d[3])
        : "r"(a.x), "r"(a.y), "r"(a.z), "r"(a.w), "r"(b.x), "r"(b.y));
}

__device__ __forceinline__ void split2(float a, float b, uint32_t& hi, uint32_t& lo) {
    __nv_bfloat16 ha = __float2bfloat16(a), hb = __float2bfloat16(b);
    float ra = a - __bfloat162float(ha), rb = b - __bfloat162float(hb);
    __nv_bfloat16 la = __float2bfloat16(ra), lb = __float2bfloat16(rb);
    hi = (uint32_t)__bfloat16_as_ushort(ha) | ((uint32_t)__bfloat16_as_ushort(hb) << 16);
    lo = (uint32_t)__bfloat16_as_ushort(la) | ((uint32_t)__bfloat16_as_ushort(lb) << 16);
}

// ---------------- pre-pack kernels (verified R8) ----------------
__global__ void pack_w1_kernel(const float* __restrict__ w_qkv) {
    const int gid = blockIdx.x * 256 + threadIdx.x;     // 0..49151
    const int lane = gid & 31;
    const int kt   = (gid >> 5) & 15;
    const int nt   = (gid >> 9) % 12;
    const int h    = (gid >> 9) / 12;
    const int c    = nt * 8 + (lane >> 2);
    const int grow = (c >> 5) * 256 + h * 32 + (c & 31);
    const int k0   = kt * 16 + (lane & 3) * 2;
    const float a0 = w_qkv[grow * 256 + k0],     a1 = w_qkv[grow * 256 + k0 + 1];
    const float b0 = w_qkv[grow * 256 + k0 + 8], b1 = w_qkv[grow * 256 + k0 + 9];
    uint32_t hx, lx, hy, ly;
    split2(a0, a1, hx, lx);
    split2(b0, b1, hy, ly);
    gW1h[gid] = make_uint2(hx, hy);
    gW1l[gid] = make_uint2(lx, ly);
}

__global__ void pack_w2_kernel(const float* __restrict__ w_proj) {
    const int gid = blockIdx.x * 256 + threadIdx.x;     // 0..16383
    const int lane = gid & 31;
    const int kt   = (gid >> 5) & 1;
    const int nt   = (gid >> 6) & 31;
    const int h    = gid >> 11;
    const int n    = nt * 8 + (lane >> 2);
    const int k    = h * 32 + kt * 16 + (lane & 3) * 2;
    const float a0 = w_proj[n * 256 + k],     a1 = w_proj[n * 256 + k + 1];
    const float b0 = w_proj[n * 256 + k + 8], b1 = w_proj[n * 256 + k + 9];
    uint32_t hx, lx, hy, ly;
    split2(a0, a1, hx, lx);
    split2(b0, b1, hy, ly);
    gW2h[gid] = make_uint2(hx, hy);
    gW2l[gid] = make_uint2(lx, ly);
}

__device__ __forceinline__ int row_gbase(int win, int tok) {
    const int b  = win / 576;
    const int wh = (win % 576) / 24;
    const int ww = win % 24;
    return ((b * 192 + wh * 8 + (tok >> 3)) * 192 + (ww * 8 + (tok & 7))) * 256;
}

__global__ __launch_bounds__(256, 1)
void win_mhsa_mma_kernel(const float* __restrict__ x,
                         const float* __restrict__ b_qkv,
                         const float* __restrict__ b_proj,
                         float* __restrict__ out)
{
    extern __shared__ char smc[];
    float* sQT[2] = { (float*)(smc + SQT0_B), (float*)(smc + SQT1_B) };
    float* sKT[2] = { (float*)(smc + SKT0_B), (float*)(smc + SKT1_B) };
    float* sV[2]  = { (float*)(smc + SV0_B),  (float*)(smc + SV1_B)  };
    float* sS[2]  = { (float*)(smc + SS0_B),  (float*)(smc + SS1_B)  };
    float* sP[2]  = { (float*)(smc + SP0_B),  (float*)(smc + SP1_B)  };
    float* sBiasQ = (float*)(smc + SBIASQ_B);
    float* sBiasP = (float*)(smc + SBIASP_B);
    const int opOff[2] = { OP0_B, OP1_B };

    const int tid  = threadIdx.x;
    const int wid  = tid >> 5;
    const int lane = tid & 31;
    const int win  = blockIdx.x;
    const float QSCALE = 0.17677669529663689f;   // 32^-0.5

    // all biases staged once (before the first barrier)
    sBiasP[tid] = __ldg(&b_proj[tid]);
    sBiasQ[tid] = __ldg(&b_qkv[tid]);
    sBiasQ[tid + 256] = __ldg(&b_qkv[tid + 256]);
    sBiasQ[tid + 512] = __ldg(&b_qkv[tid + 512]);

    // ---------------- X window -> A-fragment pack (hi/lo bf16) ----------------
    {
        const int row = tid >> 2, p = tid & 3;
        const float4* gx = reinterpret_cast<const float4*>(x + row_gbase(win, row));
        const int mt = row >> 4, rin = row & 15, g = rin & 7, rh = rin >> 3;
        #pragma unroll
        for (int u = 0; u < 16; u++) {
            const int k4 = p * 16 + u;
            const float4 v = __ldg(&gx[k4]);
            const int ktile = k4 >> 2;
            const int cpair = (k4 & 3) * 2;
            const float e[4] = { v.x, v.y, v.z, v.w };
            #pragma unroll
            for (int pr = 0; pr < 2; pr++) {
                const int cp = cpair + pr, c8 = cp >> 2, cc = cp & 3;
                const int laneX = g * 4 + cc, slot = rh + 2 * c8;
                uint32_t hi, lo;
                split2(e[pr * 2], e[pr * 2 + 1], hi, lo);
                char* base = smc + XP_B + (((mt * 16 + ktile) * 32 + laneX) << 4) + slot * 4;
                *reinterpret_cast<uint32_t*>(base)         = hi;
                *reinterpret_cast<uint32_t*>(base + 32768) = lo;
            }
        }
    }
    __syncthreads();

    const int mw = wid & 3;      // M-tile (16 tokens)
    const int nh = wid >> 2;     // N-half

    float acc2[16][4];
    #pragma unroll
    for (int i = 0; i < 16; i++)
        #pragma unroll
        for (int j = 0; j < 4; j++) acc2[i][j] = 0.0f;

    for (int hp = 0; hp < 4; hp++) {
        const int h0 = hp * 2, h1 = h0 + 1;

        // ===== GEMM1 (both heads): QKV[64,96] = X @ Wh^T =====
        float acc1[2][6][4];
        #pragma unroll
        for (int hh = 0; hh < 2; hh++)
            #pragma unroll
            for (int i = 0; i < 6; i++)
                #pragma unroll
                for (int j = 0; j < 4; j++) acc1[hh][i][j] = 0.0f;
        {
            const uint2* w1h0 = gW1h + ((h0 * 12 + nh * 6) * 16) * 32 + lane;
            const uint2* w1l0 = gW1l + ((h0 * 12 + nh * 6) * 16) * 32 + lane;
            const uint2* w1h1 = gW1h + ((h1 * 12 + nh * 6) * 16) * 32 + lane;
            const uint2* w1l1 = gW1l + ((h1 * 12 + nh * 6) * 16) * 32 + lane;
            #pragma unroll 4
            for (int kt = 0; kt < 16; kt++) {
                const char* ab = smc + XP_B + (((mw * 16 + kt) * 32 + lane) << 4);
                const uint4 Ah = *reinterpret_cast<const uint4*>(ab);
                const uint4 Al = *reinterpret_cast<const uint4*>(ab + 32768);
                #pragma unroll
                for (int nt = 0; nt < 6; nt++) {
                    const uint2 Bh0 = __ldg(&w1h0[(nt * 16 + kt) * 32]);
                    const uint2 Bl0 = __ldg(&w1l0[(nt * 16 + kt) * 32]);
                    const uint2 Bh1 = __ldg(&w1h1[(nt * 16 + kt) * 32]);
                    const uint2 Bl1 = __ldg(&w1l1[(nt * 16 + kt) * 32]);
                    mma16816(acc1[0][nt], Ah, Bh0);
                    mma16816(acc1[1][nt], Ah, Bh1);
                    mma16816(acc1[0][nt], Ah, Bl0);
                    mma16816(acc1[1][nt], Ah, Bl1);
                    mma16816(acc1[0][nt], Al, Bh0);
                    mma16816(acc1[1][nt], Al, Bh1);
                }
            }
        }
        // scatter QKV (+bias) for both heads
        {
            const int g = lane >> 2, c = (lane & 3) * 2;
            #pragma unroll
            for (int hh = 0; hh < 2; hh++) {
                const int h = h0 + hh;
                #pragma unroll
                for (int nt = 0; nt < 6; nt++) {
                    const int colb = (nh * 6 + nt) * 8 + c;
                    #pragma unroll
                    for (int e = 0; e < 4; e++) {
                        const int col = colb + (e & 1);
                        const int tok = mw * 16 + g + (e >> 1) * 8;
                        const float v = acc1[hh][nt][e] +
                                        sBiasQ[(col >> 5) * 256 + h * 32 + (col & 31)];
                        if (col < 32)       sQT[hh][col * 64 + tok] = v * QSCALE;
                        else if (col < 64)  sKT[hh][(col - 32) * 64 + tok] = v;
                        else                sV[hh][tok * 34 + (col - 64)] = v;
                    }
                }
            }
        }
        __syncthreads();

        // ===== S = Q K^T (both heads, 4x4 microtiles) =====
        const int tg = tid >> 4, cg = tid & 15;
        const int t0 = tg * 4, j0 = cg * 4, d0 = cg * 2;
        {
            float s0[4][4], s1[4][4];
            #pragma unroll
            for (int m = 0; m < 4; m++)
                #pragma unroll
                for (int n = 0; n < 4; n++) { s0[m][n] = 0.0f; s1[m][n] = 0.0f; }
            #pragma unroll
            for (int d = 0; d < 32; d++) {
                const float4 qa0 = *reinterpret_cast<const float4*>(&sQT[0][d * 64 + t0]);
                const float4 kb0 = *reinterpret_cast<const float4*>(&sKT[0][d * 64 + j0]);
                const float4 qa1 = *reinterpret_cast<const float4*>(&sQT[1][d * 64 + t0]);
                const float4 kb1 = *reinterpret_cast<const float4*>(&sKT[1][d * 64 + j0]);
                const float q0[4] = { qa0.x, qa0.y, qa0.z, qa0.w };
                const float k0v[4] = { kb0.x, kb0.y, kb0.z, kb0.w };
                const float q1[4] = { qa1.x, qa1.y, qa1.z, qa1.w };
                const float k1v[4] = { kb1.x, kb1.y, kb1.z, kb1.w };
                #pragma unroll
                for (int m = 0; m < 4; m++)
                    #pragma unroll
                    for (int n = 0; n < 4; n++) {
                        s0[m][n] += q0[m] * k0v[n];
                        s1[m][n] += q1[m] * k1v[n];
                    }
            }
            #pragma unroll
            for (int m = 0; m < 4; m++) {
                *reinterpret_cast<float4*>(&sS[0][(t0 + m) * 68 + j0]) =
                    make_float4(s0[m][0], s0[m][1], s0[m][2], s0[m][3]);
                *reinterpret_cast<float4*>(&sS[1][(t0 + m) * 68 + j0]) =
                    make_float4(s1[m][0], s1[m][1], s1[m][2], s1[m][3]);
            }
        }
        __syncthreads();

        // ===== softmax rows (both heads) -> P^T =====
        {
            const int r = tid >> 2, p = tid & 3;
            float v0[16], v1[16];
            const float* row0 = &sS[0][r * 68 + p * 16];
            const float* row1 = &sS[1][r * 68 + p * 16];
            #pragma unroll
            for (int u = 0; u < 4; u++) {
                const float4 f0 = *reinterpret_cast<const float4*>(row0 + u * 4);
                const float4 f1 = *reinterpret_cast<const float4*>(row1 + u * 4);
                v0[u*4+0]=f0.x; v0[u*4+1]=f0.y; v0[u*4+2]=f0.z; v0[u*4+3]=f0.w;
                v1[u*4+0]=f1.x; v1[u*4+1]=f1.y; v1[u*4+2]=f1.z; v1[u*4+3]=f1.w;
            }
            float m0 = v0[0], m1 = v1[0];
            #pragma unroll
            for (int i = 1; i < 16; i++) { m0 = fmaxf(m0, v0[i]); m1 = fmaxf(m1, v1[i]); }
            m0 = fmaxf(m0, __shfl_xor_sync(0xffffffffu, m0, 1));
            m1 = fmaxf(m1, __shfl_xor_sync(0xffffffffu, m1, 1));
            m0 = fmaxf(m0, __shfl_xor_sync(0xffffffffu, m0, 2));
            m1 = fmaxf(m1, __shfl_xor_sync(0xffffffffu, m1, 2));
            float sm0 = 0.0f, sm1 = 0.0f;
            #pragma unroll
            for (int i = 0; i < 16; i++) {
                v0[i] = __expf(v0[i] - m0); sm0 += v0[i];
                v1[i] = __expf(v1[i] - m1); sm1 += v1[i];
            }
            sm0 += __shfl_xor_sync(0xffffffffu, sm0, 1);
            sm1 += __shfl_xor_sync(0xffffffffu, sm1, 1);
            sm0 += __shfl_xor_sync(0xffffffffu, sm0, 2);
            sm1 += __shfl_xor_sync(0xffffffffu, sm1, 2);
            const float i0 = 1.0f / sm0, i1 = 1.0f / sm1;
            #pragma unroll
            for (int i = 0; i < 16; i++) {
                sP[0][(p * 16 + i) * 68 + r] = v0[i] * i0;
                sP[1][(p * 16 + i) * 68 + r] = v1[i] * i1;
            }
        }
        __syncthreads();

        // ===== O = P V (both heads) -> OPack =====
        {
            float o0[4][2], o1[4][2];
            #pragma unroll
            for (int m = 0; m < 4; m++) { o0[m][0]=o0[m][1]=0.0f; o1[m][0]=o1[m][1]=0.0f; }
            #pragma unroll 4
            for (int j = 0; j < 64; j++) {
                const float4 pa0 = *reinterpret_cast<const float4*>(&sP[0][j * 68 + t0]);
                const float2 vb0 = *reinterpret_cast<const float2*>(&sV[0][j * 34 + d0]);
                const float4 pa1 = *reinterpret_cast<const float4*>(&sP[1][j * 68 + t0]);
                const float2 vb1 = *reinterpret_cast<const float2*>(&sV[1][j * 34 + d0]);
                const float p0[4] = { pa0.x, pa0.y, pa0.z, pa0.w };
                const float p1[4] = { pa1.x, pa1.y, pa1.z, pa1.w };
                #pragma unroll
                for (int m = 0; m < 4; m++) {
                    o0[m][0] += p0[m] * vb0.x;  o0[m][1] += p0[m] * vb0.y;
                    o1[m][0] += p1[m] * vb1.x;  o1[m][1] += p1[m] * vb1.y;
                }
            }
            const int ktile = cg >> 3, cpr = cg & 7;
            const int c8 = cpr >> 2, cc = cpr & 3;
            #pragma unroll
            for (int m = 0; m < 4; m++) {
                const int r = t0 + m;
                const int mt = r >> 4, rin = r & 15, g = rin & 7, rh = rin >> 3;
                const int laneO = g * 4 + cc, slot = rh + 2 * c8;
                uint32_t hi, lo;
                split2(o0[m][0], o0[m][1], hi, lo);
                char* b0p = smc + opOff[0] + (((mt * 2 + ktile) * 32 + laneO) << 4) + slot * 4;
                *reinterpret_cast<uint32_t*>(b0p)        = hi;
                *reinterpret_cast<uint32_t*>(b0p + 4096) = lo;
                split2(o1[m][0], o1[m][1], hi, lo);
                char* b1p = smc + opOff[1] + (((mt * 2 + ktile) * 32 + laneO) << 4) + slot * 4;
                *reinterpret_cast<uint32_t*>(b1p)        = hi;
                *reinterpret_cast<uint32_t*>(b1p + 4096) = lo;
            }
        }
        __syncthreads();

        // ===== GEMM2 (both heads): Y += O_h @ Wproj_h^T (reg accumulate) =====
        #pragma unroll
        for (int hh = 0; hh < 2; hh++) {
            const int h = h0 + hh;
            const uint2* w2h = gW2h + ((h * 32 + nh * 16) * 2) * 32 + lane;
            const uint2* w2l = gW2l + ((h * 32 + nh * 16) * 2) * 32 + lane;
            #pragma unroll
            for (int kt = 0; kt < 2; kt++) {
                const char* ab = smc + opOff[hh] + (((mw * 2 + kt) * 32 + lane) << 4);
                const uint4 Ah = *reinterpret_cast<const uint4*>(ab);
                const uint4 Al = *reinterpret_cast<const uint4*>(ab + 4096);
                #pragma unroll
                for (int nt = 0; nt < 16; nt++) {
                    const uint2 Bh = __ldg(&w2h[(nt * 2 + kt) * 32]);
                    const uint2 Bl = __ldg(&w2l[(nt * 2 + kt) * 32]);
                    mma16816(acc2[nt], Ah, Bh);
                    mma16816(acc2[nt], Ah, Bl);
                    mma16816(acc2[nt], Al, Bh);
                }
            }
        }
        // no barrier needed: next pair's OP writes are ordered by 3 intervening barriers
    } // head pairs

    // ---------------- epilogue: Y + b_proj -> global ----------------
    {
        const int g = lane >> 2, c = (lane & 3) * 2;
        const int tok0 = mw * 16 + g, tok1 = tok0 + 8;
        float* g0 = out + row_gbase(win, tok0);
        float* g1 = out + row_gbase(win, tok1);
        #pragma unroll
        for (int nt = 0; nt < 16; nt++) {
            const int colb = (nh * 16 + nt) * 8 + c;
            const float b0 = sBiasP[colb], b1 = sBiasP[colb + 1];
            float2 v0 = make_float2(acc2[nt][0] + b0, acc2[nt][1] + b1);
            float2 v1 = make_float2(acc2[nt][2] + b0, acc2[nt][3] + b1);
            *reinterpret_cast<float2*>(g0 + colb) = v0;
            *reinterpret_cast<float2*>(g1 + colb) = v1;
        }
    }
}

extern "C" void kernel_launch(void* const* d_in, const int* in_sizes, int n_in,
                              void* d_out, int out_size)
{
    const float* x      = (const float*)d_in[0];
    const float* w_qkv  = (const float*)d_in[1];
    const float* b_qkv  = (const float*)d_in[2];
    const float* w_proj = (const float*)d_in[3];
    const float* b_proj = (const float*)d_in[4];
    float* out = (float*)d_out;
    (void)in_sizes; (void)n_in; (void)out_size;

    pack_w1_kernel<<<192, 256>>>(w_qkv);
    pack_w2_kernel<<<64, 256>>>(w_proj);

    cudaFuncSetAttribute(win_mhsa_mma_kernel,
                         cudaFuncAttributeMaxDynamicSharedMemorySize, SMEM_TOTAL);
    win_mhsa_mma_kernel<<<NWIN, 256, SMEM_TOTAL>>>(x, b_qkv, b_proj, out);
}

// round 15
// speedup vs baseline: 1.2167x; 1.0462x over previous
#include <cuda_runtime.h>
#include <cuda_bf16.h>
#include <cstdint>

// LocalAttention2D: windowed MHSA, fully tensorized GEMMs (mma.sync bf16 hi/lo
// split, 3-term, fp32 accum) including S=QK^T and O=PV. Softmax in fp32 SIMT.
// One window per CTA, 256 threads, heads in pairs (4 barriers/pair).
// Weights pre-packed to fragment layout in gmem (L2-resident).

#define NWIN 4608

// ---- SMEM byte layout ----
#define XP_B      0        // X A-frag pack: [2 plane][4 mt][16 kt][32][16B] = 65536
#define OP0_B     65536    // O A-frag pack head0 (2 planes x 4096) = 8192
#define OP1_B     73728
#define QA0_B     81920    // Q A-frag pack: [2 plane][4 mt][2 kt][32][16B] = 8192
#define QA1_B     90112
#define KB0_B     98304    // K B-frag pack: [2 plane][8 nt][2 kt][32][8B] = 8192
#define KB1_B     106496
#define PA0_B     114688   // P A-frag pack: [2 plane][4 mt][4 kt][32][16B] = 16384
#define PA1_B     131072
#define SV0_B     147456   // V planar [64 tok][34 d] f32 = 8704
#define SV1_B     156160
#define SS0_B     164864   // S [64][68] f32 = 17408
#define SS1_B     182272
#define SBIASQ_B  199680   // 768 f32
#define SBIASP_B  202752   // 256 f32
#define SMEM_TOTAL 203776

// ---- global packed weight buffers (B-fragment layout, bf16 hi/lo planes) ----
__device__ uint2 gW1h[8 * 12 * 16 * 32];
__device__ uint2 gW1l[8 * 12 * 16 * 32];
__device__ uint2 gW2h[8 * 32 * 2 * 32];
__device__ uint2 gW2l[8 * 32 * 2 * 32];

__device__ __forceinline__ void mma16816(float* d, const uint4 a, const uint2 b) {
    asm volatile(
        "mma.sync.aligned.m16n8k16.row.col.f32.bf16.bf16.f32 "
        "{%0,%1,%2,%3}, {%4,%5,%6,%7}, {%8,%9}, {%0,%1,%2,%3};\n"
        : "+f"(d[0]), "+f"(d[1]), "+f"(d[2]), "+f"(d[3])
        : "r"(a.x), "r"(a.y), "r"(a.z), "r"(a.w), "r"(b.x), "r"(b.y));
}

__device__ __forceinline__ void split2(float a, float b, uint32_t& hi, uint32_t& lo) {
    __nv_bfloat16 ha = __float2bfloat16(a), hb = __float2bfloat16(b);
    float ra = a - __bfloat162float(ha), rb = b - __bfloat162float(hb);
    __nv_bfloat16 la = __float2bfloat16(ra), lb = __float2bfloat16(rb);
    hi = (uint32_t)__bfloat16_as_ushort(ha) | ((uint32_t)__bfloat16_as_ushort(hb) << 16);
    lo = (uint32_t)__bfloat16_as_ushort(la) | ((uint32_t)__bfloat16_as_ushort(lb) << 16);
}

// ---------------- pre-pack kernels (verified R8) ----------------
__global__ void pack_w1_kernel(const float* __restrict__ w_qkv) {
    const int gid = blockIdx.x * 256 + threadIdx.x;     // 0..49151
    const int lane = gid & 31;
    const int kt   = (gid >> 5) & 15;
    const int nt   = (gid >> 9) % 12;
    const int h    = (gid >> 9) / 12;
    const int c    = nt * 8 + (lane >> 2);
    const int grow = (c >> 5) * 256 + h * 32 + (c & 31);
    const int k0   = kt * 16 + (lane & 3) * 2;
    const float a0 = w_qkv[grow * 256 + k0],     a1 = w_qkv[grow * 256 + k0 + 1];
    const float b0 = w_qkv[grow * 256 + k0 + 8], b1 = w_qkv[grow * 256 + k0 + 9];
    uint32_t hx, lx, hy, ly;
    split2(a0, a1, hx, lx);
    split2(b0, b1, hy, ly);
    gW1h[gid] = make_uint2(hx, hy);
    gW1l[gid] = make_uint2(lx, ly);
}

__global__ void pack_w2_kernel(const float* __restrict__ w_proj) {
    const int gid = blockIdx.x * 256 + threadIdx.x;     // 0..16383
    const int lane = gid & 31;
    const int kt   = (gid >> 5) & 1;
    const int nt   = (gid >> 6) & 31;
    const int h    = gid >> 11;
    const int n    = nt * 8 + (lane >> 2);
    const int k    = h * 32 + kt * 16 + (lane & 3) * 2;
    const float a0 = w_proj[n * 256 + k],     a1 = w_proj[n * 256 + k + 1];
    const float b0 = w_proj[n * 256 + k + 8], b1 = w_proj[n * 256 + k + 9];
    uint32_t hx, lx, hy, ly;
    split2(a0, a1, hx, lx);
    split2(b0, b1, hy, ly);
    gW2h[gid] = make_uint2(hx, hy);
    gW2l[gid] = make_uint2(lx, ly);
}

__device__ __forceinline__ int row_gbase(int win, int tok) {
    const int b  = win / 576;
    const int wh = (win % 576) / 24;
    const int ww = win % 24;
    return ((b * 192 + wh * 8 + (tok >> 3)) * 192 + (ww * 8 + (tok & 7))) * 256;
}

__global__ __launch_bounds__(256, 1)
void win_mhsa_mma_kernel(const float* __restrict__ x,
                         const float* __restrict__ b_qkv,
                         const float* __restrict__ b_proj,
                         float* __restrict__ out)
{
    extern __shared__ char smc[];
    float* sV[2] = { (float*)(smc + SV0_B), (float*)(smc + SV1_B) };
    float* sS[2] = { (float*)(smc + SS0_B), (float*)(smc + SS1_B) };
    float* sBiasQ = (float*)(smc + SBIASQ_B);
    float* sBiasP = (float*)(smc + SBIASP_B);
    const int opB[2] = { OP0_B, OP1_B };
    const int qaB[2] = { QA0_B, QA1_B };
    const int kbB[2] = { KB0_B, KB1_B };
    const int paB[2] = { PA0_B, PA1_B };

    const int tid  = threadIdx.x;
    const int wid  = tid >> 5;
    const int lane = tid & 31;
    const int win  = blockIdx.x;
    const float QSCALE = 0.17677669529663689f;   // 32^-0.5

    sBiasP[tid] = __ldg(&b_proj[tid]);
    sBiasQ[tid] = __ldg(&b_qkv[tid]);
    sBiasQ[tid + 256] = __ldg(&b_qkv[tid + 256]);
    sBiasQ[tid + 512] = __ldg(&b_qkv[tid + 512]);

    // ---------------- X window -> A-fragment pack (hi/lo bf16) ----------------
    {
        const int row = tid >> 2, p = tid & 3;
        const float4* gx = reinterpret_cast<const float4*>(x + row_gbase(win, row));
        const int mt = row >> 4, rin = row & 15, g = rin & 7, rh = rin >> 3;
        #pragma unroll
        for (int u = 0; u < 16; u++) {
            const int k4 = p * 16 + u;
            const float4 v = __ldg(&gx[k4]);
            const int ktile = k4 >> 2;
            const int cpair = (k4 & 3) * 2;
            const float e[4] = { v.x, v.y, v.z, v.w };
            #pragma unroll
            for (int pr = 0; pr < 2; pr++) {
                const int cp = cpair + pr, c8 = cp >> 2, cc = cp & 3;
                const int laneX = g * 4 + cc, slot = rh + 2 * c8;
                uint32_t hi, lo;
                split2(e[pr * 2], e[pr * 2 + 1], hi, lo);
                char* base = smc + XP_B + (((mt * 16 + ktile) * 32 + laneX) << 4) + slot * 4;
                *reinterpret_cast<uint32_t*>(base)         = hi;
                *reinterpret_cast<uint32_t*>(base + 32768) = lo;
            }
        }
    }
    __syncthreads();

    const int mw = wid & 3;      // M-tile (16 tokens)
    const int nh = wid >> 2;     // N-half
    const int g  = lane >> 2;    // row-in-8 group

    float acc2[16][4];
    #pragma unroll
    for (int i = 0; i < 16; i++)
        #pragma unroll
        for (int j = 0; j < 4; j++) acc2[i][j] = 0.0f;

    for (int hp = 0; hp < 4; hp++) {
        const int h0 = hp * 2, h1 = h0 + 1;

        // ===== GEMM1 (both heads): QKV[64,96] = X @ Wh^T =====
        float acc1[2][6][4];
        #pragma unroll
        for (int hh = 0; hh < 2; hh++)
            #pragma unroll
            for (int i = 0; i < 6; i++)
                #pragma unroll
                for (int j = 0; j < 4; j++) acc1[hh][i][j] = 0.0f;
        {
            const uint2* w1h0 = gW1h + ((h0 * 12 + nh * 6) * 16) * 32 + lane;
            const uint2* w1l0 = gW1l + ((h0 * 12 + nh * 6) * 16) * 32 + lane;
            const uint2* w1h1 = gW1h + ((h1 * 12 + nh * 6) * 16) * 32 + lane;
            const uint2* w1l1 = gW1l + ((h1 * 12 + nh * 6) * 16) * 32 + lane;
            #pragma unroll 4
            for (int kt = 0; kt < 16; kt++) {
                const char* ab = smc + XP_B + (((mw * 16 + kt) * 32 + lane) << 4);
                const uint4 Ah = *reinterpret_cast<const uint4*>(ab);
                const uint4 Al = *reinterpret_cast<const uint4*>(ab + 32768);
                #pragma unroll
                for (int nt = 0; nt < 6; nt++) {
                    const uint2 Bh0 = __ldg(&w1h0[(nt * 16 + kt) * 32]);
                    const uint2 Bl0 = __ldg(&w1l0[(nt * 16 + kt) * 32]);
                    const uint2 Bh1 = __ldg(&w1h1[(nt * 16 + kt) * 32]);
                    const uint2 Bl1 = __ldg(&w1l1[(nt * 16 + kt) * 32]);
                    mma16816(acc1[0][nt], Ah, Bh0);
                    mma16816(acc1[1][nt], Ah, Bh1);
                    mma16816(acc1[0][nt], Ah, Bl0);
                    mma16816(acc1[1][nt], Ah, Bl1);
                    mma16816(acc1[0][nt], Al, Bh0);
                    mma16816(acc1[1][nt], Al, Bh1);
                }
            }
        }
        // scatter QKV (+bias) into fragment packs (Q: A-frag, K: B-frag, V: planar)
        {
            #pragma unroll
            for (int hh = 0; hh < 2; hh++) {
                const int h = h0 + hh;
                #pragma unroll
                for (int nt = 0; nt < 6; nt++) {
                    const int q = nh * 6 + nt;            // 0..11 col-octet
                    const int colb = q * 8 + (lane & 3) * 2;
                    float v0 = acc1[hh][nt][0] + sBiasQ[((colb    ) >> 5) * 256 + h * 32 + ((colb    ) & 31)];
                    float v1 = acc1[hh][nt][1] + sBiasQ[((colb + 1) >> 5) * 256 + h * 32 + ((colb + 1) & 31)];
                    float v2 = acc1[hh][nt][2] + sBiasQ[((colb    ) >> 5) * 256 + h * 32 + ((colb    ) & 31)];
                    float v3 = acc1[hh][nt][3] + sBiasQ[((colb + 1) >> 5) * 256 + h * 32 + ((colb + 1) & 31)];
                    if (q < 4) {
                        // Q: scale then A-frag pack
                        v0 *= QSCALE; v1 *= QSCALE; v2 *= QSCALE; v3 *= QSCALE;
                        const int kt = q >> 1, c8 = q & 1;
                        uint32_t h01, l01, h23, l23;
                        split2(v0, v1, h01, l01);
                        split2(v2, v3, h23, l23);
                        char* base = smc + qaB[hh] + (((mw * 2 + kt) * 32 + lane) << 4);
                        *reinterpret_cast<uint32_t*>(base + (0 + 2 * c8) * 4)        = h01;
                        *reinterpret_cast<uint32_t*>(base + (1 + 2 * c8) * 4)        = h23;
                        *reinterpret_cast<uint32_t*>(base + (0 + 2 * c8) * 4 + 4096) = l01;
                        *reinterpret_cast<uint32_t*>(base + (1 + 2 * c8) * 4 + 4096) = l23;
                    } else if (q < 8) {
                        // K: B-frag pack. rows t=mw*16+g -> ntj=mw*2 ; t+8 -> ntj=mw*2+1
                        const int kt = (q - 4) >> 1, w = (q - 4) & 1;
                        uint32_t hi, lo;
                        split2(v0, v1, hi, lo);
                        char* b0 = smc + kbB[hh] + ((((mw * 2 + 0) * 2 + kt) * 32 + lane) << 3) + w * 4;
                        *reinterpret_cast<uint32_t*>(b0)        = hi;
                        *reinterpret_cast<uint32_t*>(b0 + 4096) = lo;
                        split2(v2, v3, hi, lo);
                        char* b1 = smc + kbB[hh] + ((((mw * 2 + 1) * 2 + kt) * 32 + lane) << 3) + w * 4;
                        *reinterpret_cast<uint32_t*>(b1)        = hi;
                        *reinterpret_cast<uint32_t*>(b1 + 4096) = lo;
                    } else {
                        // V: planar [tok][34]
                        const int d = (q - 8) * 8 + (lane & 3) * 2;
                        const int t = mw * 16 + g;
                        *reinterpret_cast<float2*>(&sV[hh][t * 34 + d])       = make_float2(v0, v1);
                        *reinterpret_cast<float2*>(&sV[hh][(t + 8) * 34 + d]) = make_float2(v2, v3);
                    }
                }
            }
        }
        __syncthreads();

        // ===== S = Q K^T via HMMA (warp (mw, jh=nh): rows mw*16.., cols nh*32..) =====
        {
            #pragma unroll
            for (int hh = 0; hh < 2; hh++) {
                uint4 Ah[2], Al[2];
                #pragma unroll
                for (int kt = 0; kt < 2; kt++) {
                    const char* qb = smc + qaB[hh] + (((mw * 2 + kt) * 32 + lane) << 4);
                    Ah[kt] = *reinterpret_cast<const uint4*>(qb);
                    Al[kt] = *reinterpret_cast<const uint4*>(qb + 4096);
                }
                #pragma unroll
                for (int ntl = 0; ntl < 4; ntl++) {
                    const int ntj = nh * 4 + ntl;
                    float sacc[4] = { 0.0f, 0.0f, 0.0f, 0.0f };
                    #pragma unroll
                    for (int kt = 0; kt < 2; kt++) {
                        const char* kb = smc + kbB[hh] + (((ntj * 2 + kt) * 32 + lane) << 3);
                        const uint2 Bh = *reinterpret_cast<const uint2*>(kb);
                        const uint2 Bl = *reinterpret_cast<const uint2*>(kb + 4096);
                        mma16816(sacc, Ah[kt], Bh);
                        mma16816(sacc, Ah[kt], Bl);
                        mma16816(sacc, Al[kt], Bh);
                    }
                    const int t = mw * 16 + g;
                    const int j = ntj * 8 + (lane & 3) * 2;
                    *reinterpret_cast<float2*>(&sS[hh][t * 68 + j])       = make_float2(sacc[0], sacc[1]);
                    *reinterpret_cast<float2*>(&sS[hh][(t + 8) * 68 + j]) = make_float2(sacc[2], sacc[3]);
                }
            }
        }
        __syncthreads();

        // ===== softmax rows (both heads) -> P A-frag pack =====
        {
            const int r = tid >> 2, p = tid & 3;
            float v0[16], v1[16];
            const float* row0 = &sS[0][r * 68 + p * 16];
            const float* row1 = &sS[1][r * 68 + p * 16];
            #pragma unroll
            for (int u = 0; u < 4; u++) {
                const float4 f0 = *reinterpret_cast<const float4*>(row0 + u * 4);
                const float4 f1 = *reinterpret_cast<const float4*>(row1 + u * 4);
                v0[u*4+0]=f0.x; v0[u*4+1]=f0.y; v0[u*4+2]=f0.z; v0[u*4+3]=f0.w;
                v1[u*4+0]=f1.x; v1[u*4+1]=f1.y; v1[u*4+2]=f1.z; v1[u*4+3]=f1.w;
            }
            float m0 = v0[0], m1 = v1[0];
            #pragma unroll
            for (int i = 1; i < 16; i++) { m0 = fmaxf(m0, v0[i]); m1 = fmaxf(m1, v1[i]); }
            m0 = fmaxf(m0, __shfl_xor_sync(0xffffffffu, m0, 1));
            m1 = fmaxf(m1, __shfl_xor_sync(0xffffffffu, m1, 1));
            m0 = fmaxf(m0, __shfl_xor_sync(0xffffffffu, m0, 2));
            m1 = fmaxf(m1, __shfl_xor_sync(0xffffffffu, m1, 2));
            float sm0 = 0.0f, sm1 = 0.0f;
            #pragma unroll
            for (int i = 0; i < 16; i++) {
                v0[i] = __expf(v0[i] - m0); sm0 += v0[i];
                v1[i] = __expf(v1[i] - m1); sm1 += v1[i];
            }
            sm0 += __shfl_xor_sync(0xffffffffu, sm0, 1);
            sm1 += __shfl_xor_sync(0xffffffffu, sm1, 1);
            sm0 += __shfl_xor_sync(0xffffffffu, sm0, 2);
            sm1 += __shfl_xor_sync(0xffffffffu, sm1, 2);
            const float i0 = 1.0f / sm0, i1 = 1.0f / sm1;
            // emit P A-fragments: row r, kt = p, pairs cp = 0..7
            const int mt = r >> 4, rin = r & 15, g2 = rin & 7, rh = rin >> 3;
            #pragma unroll
            for (int cp = 0; cp < 8; cp++) {
                const int lane2 = g2 * 4 + (cp & 3);
                const int slot  = rh + 2 * (cp >> 2);
                uint32_t hi, lo;
                split2(v0[cp * 2] * i0, v0[cp * 2 + 1] * i0, hi, lo);
                char* b0 = smc + paB[0] + (((mt * 4 + p) * 32 + lane2) << 4) + slot * 4;
                *reinterpret_cast<uint32_t*>(b0)        = hi;
                *reinterpret_cast<uint32_t*>(b0 + 8192) = lo;
                split2(v1[cp * 2] * i1, v1[cp * 2 + 1] * i1, hi, lo);
                char* b1 = smc + paB[1] + (((mt * 4 + p) * 32 + lane2) << 4) + slot * 4;
                *reinterpret_cast<uint32_t*>(b1)        = hi;
                *reinterpret_cast<uint32_t*>(b1 + 8192) = lo;
            }
        }
        __syncthreads();

        // ===== O = P V via HMMA (warp (mw, dh=nh)) -> OP pack =====
        {
            #pragma unroll
            for (int hh = 0; hh < 2; hh++) {
                uint4 PAh[4], PAl[4];
                #pragma unroll
                for (int kt = 0; kt < 4; kt++) {
                    const char* pb = smc + paB[hh] + (((mw * 4 + kt) * 32 + lane) << 4);
                    PAh[kt] = *reinterpret_cast<const uint4*>(pb);
                    PAl[kt] = *reinterpret_cast<const uint4*>(pb + 8192);
                }
                #pragma unroll
                for (int ntl = 0; ntl < 2; ntl++) {
                    const int n = nh * 16 + ntl * 8 + g;   // output d column
                    float oacc[4] = { 0.0f, 0.0f, 0.0f, 0.0f };
                    #pragma unroll
                    for (int kt = 0; kt < 4; kt++) {
                        const int k0 = kt * 16 + (lane & 3) * 2;
                        const float vk  = sV[hh][k0 * 34 + n];
                        const float vk1 = sV[hh][(k0 + 1) * 34 + n];
                        const float vk8 = sV[hh][(k0 + 8) * 34 + n];
                        const float vk9 = sV[hh][(k0 + 9) * 34 + n];
                        uint32_t hw0, lw0, hw1, lw1;
                        split2(vk,  vk1, hw0, lw0);
                        split2(vk8, vk9, hw1, lw1);
                        const uint2 Bh = make_uint2(hw0, hw1);
                        const uint2 Bl = make_uint2(lw0, lw1);
                        mma16816(oacc, PAh[kt], Bh);
                        mma16816(oacc, PAh[kt], Bl);
                        mma16816(oacc, PAl[kt], Bh);
                    }
                    // O D-frag maps in-lane to OP A-frag pack: kt = dh(nh), slot = rh + 2*ntl
                    uint32_t hi, lo;
                    char* base = smc + opB[hh] + (((mw * 2 + nh) * 32 + lane) << 4);
                    split2(oacc[0], oacc[1], hi, lo);
                    *reinterpret_cast<uint32_t*>(base + (0 + 2 * ntl) * 4)        = hi;
                    *reinterpret_cast<uint32_t*>(base + (0 + 2 * ntl) * 4 + 4096) = lo;
                    split2(oacc[2], oacc[3], hi, lo);
                    *reinterpret_cast<uint32_t*>(base + (1 + 2 * ntl) * 4)        = hi;
                    *reinterpret_cast<uint32_t*>(base + (1 + 2 * ntl) * 4 + 4096) = lo;
                }
            }
        }
        __syncthreads();

        // ===== GEMM2 (both heads): Y += O_h @ Wproj_h^T (reg accumulate) =====
        #pragma unroll
        for (int hh = 0; hh < 2; hh++) {
            const int h = h0 + hh;
            const uint2* w2h = gW2h + ((h * 32 + nh * 16) * 2) * 32 + lane;
            const uint2* w2l = gW2l + ((h * 32 + nh * 16) * 2) * 32 + lane;
            #pragma unroll
            for (int kt = 0; kt < 2; kt++) {
                const char* ab = smc + opB[hh] + (((mw * 2 + kt) * 32 + lane) << 4);
                const uint4 Ah = *reinterpret_cast<const uint4*>(ab);
                const uint4 Al = *reinterpret_cast<const uint4*>(ab + 4096);
                #pragma unroll
                for (int nt = 0; nt < 16; nt++) {
                    const uint2 Bh = __ldg(&w2h[(nt * 2 + kt) * 32]);
                    const uint2 Bl = __ldg(&w2l[(nt * 2 + kt) * 32]);
                    mma16816(acc2[nt], Ah, Bh);
                    mma16816(acc2[nt], Ah, Bl);
                    mma16816(acc2[nt], Al, Bh);
                }
            }
        }
        // no barrier: next pair's pack writes are ordered by >=2 intervening barriers
    } // head pairs

    // ---------------- epilogue: Y + b_proj -> global ----------------
    {
        const int c = (lane & 3) * 2;
        const int tok0 = mw * 16 + g, tok1 = tok0 + 8;
        float* g0 = out + row_gbase(win, tok0);
        float* g1 = out + row_gbase(win, tok1);
        #pragma unroll
        for (int nt = 0; nt < 16; nt++) {
            const int colb = (nh * 16 + nt) * 8 + c;
            const float b0 = sBiasP[colb], b1 = sBiasP[colb + 1];
            float2 v0 = make_float2(acc2[nt][0] + b0, acc2[nt][1] + b1);
            float2 v1 = make_float2(acc2[nt][2] + b0, acc2[nt][3] + b1);
            *reinterpret_cast<float2*>(g0 + colb) = v0;
            *reinterpret_cast<float2*>(g1 + colb) = v1;
        }
    }
}

extern "C" void kernel_launch(void* const* d_in, const int* in_sizes, int n_in,
                              void* d_out, int out_size)
{
    const float* x      = (const float*)d_in[0];
    const float* w_qkv  = (const float*)d_in[1];
    const float* b_qkv  = (const float*)d_in[2];
    const float* w_proj = (const float*)d_in[3];
    const float* b_proj = (const float*)d_in[4];
    float* out = (float*)d_out;
    (void)in_sizes; (void)n_in; (void)out_size;

    pack_w1_kernel<<<192, 256>>>(w_qkv);
    pack_w2_kernel<<<64, 256>>>(w_proj);

    cudaFuncSetAttribute(win_mhsa_mma_kernel,
                         cudaFuncAttributeMaxDynamicSharedMemorySize, SMEM_TOTAL);
    win_mhsa_mma_kernel<<<NWIN, 256, SMEM_TOTAL>>>(x, b_qkv, b_proj, out);
}

// round 16
// speedup vs baseline: 1.2188x; 1.0017x over previous
#include <cuda_runtime.h>
#include <cuda_bf16.h>
#include <cstdint>

// LocalAttention2D: windowed MHSA, fully tensorized GEMMs (mma.sync bf16 hi/lo
// split, 3-term, fp32 accum) including S=QK^T and O=PV. Softmax in fp32 SIMT.
// One window per CTA, 256 threads, heads in pairs (4 barriers/pair).
// Weights pre-packed to fragment layout in gmem (L2-resident).

#define NWIN 4608

// ---- SMEM byte layout ----
#define XP_B      0        // X A-frag pack: [2 plane][4 mt][16 kt][32][16B] = 65536
#define OP0_B     65536    // O A-frag pack head0 (2 planes x 4096) = 8192
#define OP1_B     73728
#define QA0_B     81920    // Q A-frag pack: [2 plane][4 mt][2 kt][32][16B] = 8192
#define QA1_B     90112
#define KB0_B     98304    // K B-frag pack: [2 plane][8 nt][2 kt][32][8B] = 8192
#define KB1_B     106496
#define PA0_B     114688   // P A-frag pack: [2 plane][4 mt][4 kt][32][16B] = 16384
#define PA1_B     131072
#define SV0_B     147456   // V planar [64 tok][34 d] f32 = 8704
#define SV1_B     156160
#define SS0_B     164864   // S [64][68] f32 = 17408
#define SS1_B     182272
#define SBIASQ_B  199680   // 768 f32
#define SBIASP_B  202752   // 256 f32
#define SMEM_TOTAL 203776

// ---- global packed weight buffers (B-fragment layout, bf16 hi/lo planes) ----
__device__ uint2 gW1h[8 * 12 * 16 * 32];
__device__ uint2 gW1l[8 * 12 * 16 * 32];
__device__ uint2 gW2h[8 * 32 * 2 * 32];
__device__ uint2 gW2l[8 * 32 * 2 * 32];

__device__ __forceinline__ void mma16816(float* d, const uint4 a, const uint2 b) {
    asm volatile(
        "mma.sync.aligned.m16n8k16.row.col.f32.bf16.bf16.f32 "
        "{%0,%1,%2,%3}, {%4,%5,%6,%7}, {%8,%9}, {%0,%1,%2,%3};\n"
        : "+f"(d[0]), "+f"(d[1]), "+f"(d[2]), "+f"(d[3])
        : "r"(a.x), "r"(a.y), "r"(a.z), "r"(a.w), "r"(b.x), "r"(b.y));
}

__device__ __forceinline__ void split2(float a, float b, uint32_t& hi, uint32_t& lo) {
    __nv_bfloat16 ha = __float2bfloat16(a), hb = __float2bfloat16(b);
    float ra = a - __bfloat162float(ha), rb = b - __bfloat162float(hb);
    __nv_bfloat16 la = __float2bfloat16(ra), lb = __float2bfloat16(rb);
    hi = (uint32_t)__bfloat16_as_ushort(ha) | ((uint32_t)__bfloat16_as_ushort(hb) << 16);
    lo = (uint32_t)__bfloat16_as_ushort(la) | ((uint32_t)__bfloat16_as_ushort(lb) << 16);
}

// ---------------- pre-pack kernels (verified R8) ----------------
__global__ void pack_w1_kernel(const float* __restrict__ w_qkv) {
    const int gid = blockIdx.x * 256 + threadIdx.x;     // 0..49151
    const int lane = gid & 31;
    const int kt   = (gid >> 5) & 15;
    const int nt   = (gid >> 9) % 12;
    const int h    = (gid >> 9) / 12;
    const int c    = nt * 8 + (lane >> 2);
    const int grow = (c >> 5) * 256 + h * 32 + (c & 31);
    const int k0   = kt * 16 + (lane & 3) * 2;
    const float a0 = w_qkv[grow * 256 + k0],     a1 = w_qkv[grow * 256 + k0 + 1];
    const float b0 = w_qkv[grow * 256 + k0 + 8], b1 = w_qkv[grow * 256 + k0 + 9];
    uint32_t hx, lx, hy, ly;
    split2(a0, a1, hx, lx);
    split2(b0, b1, hy, ly);
    gW1h[gid] = make_uint2(hx, hy);
    gW1l[gid] = make_uint2(lx, ly);
}

__global__ void pack_w2_kernel(const float* __restrict__ w_proj) {
    const int gid = blockIdx.x * 256 + threadIdx.x;     // 0..16383
    const int lane = gid & 31;
    const int kt   = (gid >> 5) & 1;
    const int nt   = (gid >> 6) & 31;
    const int h    = gid >> 11;
    const int n    = nt * 8 + (lane >> 2);
    const int k    = h * 32 + kt * 16 + (lane & 3) * 2;
    const float a0 = w_proj[n * 256 + k],     a1 = w_proj[n * 256 + k + 1];
    const float b0 = w_proj[n * 256 + k + 8], b1 = w_proj[n * 256 + k + 9];
    uint32_t hx, lx, hy, ly;
    split2(a0, a1, hx, lx);
    split2(b0, b1, hy, ly);
    gW2h[gid] = make_uint2(hx, hy);
    gW2l[gid] = make_uint2(lx, ly);
}

__device__ __forceinline__ int row_gbase(int win, int tok) {
    const int b  = win / 576;
    const int wh = (win % 576) / 24;
    const int ww = win % 24;
    return ((b * 192 + wh * 8 + (tok >> 3)) * 192 + (ww * 8 + (tok & 7))) * 256;
}

__global__ __launch_bounds__(256, 1)
void win_mhsa_mma_kernel(const float* __restrict__ x,
                         const float* __restrict__ b_qkv,
                         const float* __restrict__ b_proj,
                         float* __restrict__ out)
{
    extern __shared__ char smc[];
    float* sV[2] = { (float*)(smc + SV0_B), (float*)(smc + SV1_B) };
    float* sS[2] = { (float*)(smc + SS0_B), (float*)(smc + SS1_B) };
    float* sBiasQ = (float*)(smc + SBIASQ_B);
    float* sBiasP = (float*)(smc + SBIASP_B);
    const int opB[2] = { OP0_B, OP1_B };
    const int qaB[2] = { QA0_B, QA1_B };
    const int kbB[2] = { KB0_B, KB1_B };
    const int paB[2] = { PA0_B, PA1_B };

    const int tid  = threadIdx.x;
    const int wid  = tid >> 5;
    const int lane = tid & 31;
    const int win  = blockIdx.x;
    const float QSCALE = 0.17677669529663689f;   // 32^-0.5

    sBiasP[tid] = __ldg(&b_proj[tid]);
    sBiasQ[tid] = __ldg(&b_qkv[tid]);
    sBiasQ[tid + 256] = __ldg(&b_qkv[tid + 256]);
    sBiasQ[tid + 512] = __ldg(&b_qkv[tid + 512]);

    // ---------------- X window -> A-fragment pack (hi/lo bf16) ----------------
    {
        const int row = tid >> 2, p = tid & 3;
        const float4* gx = reinterpret_cast<const float4*>(x + row_gbase(win, row));
        const int mt = row >> 4, rin = row & 15, g = rin & 7, rh = rin >> 3;
        #pragma unroll
        for (int u = 0; u < 16; u++) {
            const int k4 = p * 16 + u;
            const float4 v = __ldg(&gx[k4]);
            const int ktile = k4 >> 2;
            const int cpair = (k4 & 3) * 2;
            const float e[4] = { v.x, v.y, v.z, v.w };
            #pragma unroll
            for (int pr = 0; pr < 2; pr++) {
                const int cp = cpair + pr, c8 = cp >> 2, cc = cp & 3;
                const int laneX = g * 4 + cc, slot = rh + 2 * c8;
                uint32_t hi, lo;
                split2(e[pr * 2], e[pr * 2 + 1], hi, lo);
                char* base = smc + XP_B + (((mt * 16 + ktile) * 32 + laneX) << 4) + slot * 4;
                *reinterpret_cast<uint32_t*>(base)         = hi;
                *reinterpret_cast<uint32_t*>(base + 32768) = lo;
            }
        }
    }
    __syncthreads();

    const int mw = wid & 3;      // M-tile (16 tokens)
    const int nh = wid >> 2;     // N-half
    const int g  = lane >> 2;    // row-in-8 group

    float acc2[16][4];
    #pragma unroll
    for (int i = 0; i < 16; i++)
        #pragma unroll
        for (int j = 0; j < 4; j++) acc2[i][j] = 0.0f;

    for (int hp = 0; hp < 4; hp++) {
        const int h0 = hp * 2, h1 = h0 + 1;

        // ===== GEMM1 (both heads): QKV[64,96] = X @ Wh^T =====
        float acc1[2][6][4];
        #pragma unroll
        for (int hh = 0; hh < 2; hh++)
            #pragma unroll
            for (int i = 0; i < 6; i++)
                #pragma unroll
                for (int j = 0; j < 4; j++) acc1[hh][i][j] = 0.0f;
        {
            const uint2* w1h0 = gW1h + ((h0 * 12 + nh * 6) * 16) * 32 + lane;
            const uint2* w1l0 = gW1l + ((h0 * 12 + nh * 6) * 16) * 32 + lane;
            const uint2* w1h1 = gW1h + ((h1 * 12 + nh * 6) * 16) * 32 + lane;
            const uint2* w1l1 = gW1l + ((h1 * 12 + nh * 6) * 16) * 32 + lane;
            #pragma unroll 4
            for (int kt = 0; kt < 16; kt++) {
                const char* ab = smc + XP_B + (((mw * 16 + kt) * 32 + lane) << 4);
                const uint4 Ah = *reinterpret_cast<const uint4*>(ab);
                const uint4 Al = *reinterpret_cast<const uint4*>(ab + 32768);
                #pragma unroll
                for (int nt = 0; nt < 6; nt++) {
                    const uint2 Bh0 = __ldg(&w1h0[(nt * 16 + kt) * 32]);
                    const uint2 Bl0 = __ldg(&w1l0[(nt * 16 + kt) * 32]);
                    const uint2 Bh1 = __ldg(&w1h1[(nt * 16 + kt) * 32]);
                    const uint2 Bl1 = __ldg(&w1l1[(nt * 16 + kt) * 32]);
                    mma16816(acc1[0][nt], Ah, Bh0);
                    mma16816(acc1[1][nt], Ah, Bh1);
                    mma16816(acc1[0][nt], Ah, Bl0);
                    mma16816(acc1[1][nt], Ah, Bl1);
                    mma16816(acc1[0][nt], Al, Bh0);
                    mma16816(acc1[1][nt], Al, Bh1);
                }
            }
        }
        // scatter QKV (+bias) into fragment packs (Q: A-frag, K: B-frag, V: planar)
        {
            #pragma unroll
            for (int hh = 0; hh < 2; hh++) {
                const int h = h0 + hh;
                #pragma unroll
                for (int nt = 0; nt < 6; nt++) {
                    const int q = nh * 6 + nt;            // 0..11 col-octet
                    const int colb = q * 8 + (lane & 3) * 2;
                    float v0 = acc1[hh][nt][0] + sBiasQ[((colb    ) >> 5) * 256 + h * 32 + ((colb    ) & 31)];
                    float v1 = acc1[hh][nt][1] + sBiasQ[((colb + 1) >> 5) * 256 + h * 32 + ((colb + 1) & 31)];
                    float v2 = acc1[hh][nt][2] + sBiasQ[((colb    ) >> 5) * 256 + h * 32 + ((colb    ) & 31)];
                    float v3 = acc1[hh][nt][3] + sBiasQ[((colb + 1) >> 5) * 256 + h * 32 + ((colb + 1) & 31)];
                    if (q < 4) {
                        // Q: scale then A-frag pack
                        v0 *= QSCALE; v1 *= QSCALE; v2 *= QSCALE; v3 *= QSCALE;
                        const int kt = q >> 1, c8 = q & 1;
                        uint32_t h01, l01, h23, l23;
                        split2(v0, v1, h01, l01);
                        split2(v2, v3, h23, l23);
                        char* base = smc + qaB[hh] + (((mw * 2 + kt) * 32 + lane) << 4);
                        *reinterpret_cast<uint32_t*>(base + (0 + 2 * c8) * 4)        = h01;
                        *reinterpret_cast<uint32_t*>(base + (1 + 2 * c8) * 4)        = h23;
                        *reinterpret_cast<uint32_t*>(base + (0 + 2 * c8) * 4 + 4096) = l01;
                        *reinterpret_cast<uint32_t*>(base + (1 + 2 * c8) * 4 + 4096) = l23;
                    } else if (q < 8) {
                        // K: B-frag pack. rows t=mw*16+g -> ntj=mw*2 ; t+8 -> ntj=mw*2+1
                        const int kt = (q - 4) >> 1, w = (q - 4) & 1;
                        uint32_t hi, lo;
                        split2(v0, v1, hi, lo);
                        char* b0 = smc + kbB[hh] + ((((mw * 2 + 0) * 2 + kt) * 32 + lane) << 3) + w * 4;
                        *reinterpret_cast<uint32_t*>(b0)        = hi;
                        *reinterpret_cast<uint32_t*>(b0 + 4096) = lo;
                        split2(v2, v3, hi, lo);
                        char* b1 = smc + kbB[hh] + ((((mw * 2 + 1) * 2 + kt) * 32 + lane) << 3) + w * 4;
                        *reinterpret_cast<uint32_t*>(b1)        = hi;
                        *reinterpret_cast<uint32_t*>(b1 + 4096) = lo;
                    } else {
                        // V: planar [tok][34]
                        const int d = (q - 8) * 8 + (lane & 3) * 2;
                        const int t = mw * 16 + g;
                        *reinterpret_cast<float2*>(&sV[hh][t * 34 + d])       = make_float2(v0, v1);
                        *reinterpret_cast<float2*>(&sV[hh][(t + 8) * 34 + d]) = make_float2(v2, v3);
                    }
                }
            }
        }
        __syncthreads();

        // ===== S = Q K^T via HMMA (warp (mw, jh=nh): rows mw*16.., cols nh*32..) =====
        {
            #pragma unroll
            for (int hh = 0; hh < 2; hh++) {
                uint4 Ah[2], Al[2];
                #pragma unroll
                for (int kt = 0; kt < 2; kt++) {
                    const char* qb = smc + qaB[hh] + (((mw * 2 + kt) * 32 + lane) << 4);
                    Ah[kt] = *reinterpret_cast<const uint4*>(qb);
                    Al[kt] = *reinterpret_cast<const uint4*>(qb + 4096);
                }
                #pragma unroll
                for (int ntl = 0; ntl < 4; ntl++) {
                    const int ntj = nh * 4 + ntl;
                    float sacc[4] = { 0.0f, 0.0f, 0.0f, 0.0f };
                    #pragma unroll
                    for (int kt = 0; kt < 2; kt++) {
                        const char* kb = smc + kbB[hh] + (((ntj * 2 + kt) * 32 + lane) << 3);
                        const uint2 Bh = *reinterpret_cast<const uint2*>(kb);
                        const uint2 Bl = *reinterpret_cast<const uint2*>(kb + 4096);
                        mma16816(sacc, Ah[kt], Bh);
                        mma16816(sacc, Ah[kt], Bl);
                        mma16816(sacc, Al[kt], Bh);
                    }
                    const int t = mw * 16 + g;
                    const int j = ntj * 8 + (lane & 3) * 2;
                    *reinterpret_cast<float2*>(&sS[hh][t * 68 + j])       = make_float2(sacc[0], sacc[1]);
                    *reinterpret_cast<float2*>(&sS[hh][(t + 8) * 68 + j]) = make_float2(sacc[2], sacc[3]);
                }
            }
        }
        __syncthreads();

        // ===== softmax rows (both heads) -> P A-frag pack =====
        {
            const int r = tid >> 2, p = tid & 3;
            float v0[16], v1[16];
            const float* row0 = &sS[0][r * 68 + p * 16];
            const float* row1 = &sS[1][r * 68 + p * 16];
            #pragma unroll
            for (int u = 0; u < 4; u++) {
                const float4 f0 = *reinterpret_cast<const float4*>(row0 + u * 4);
                const float4 f1 = *reinterpret_cast<const float4*>(row1 + u * 4);
                v0[u*4+0]=f0.x; v0[u*4+1]=f0.y; v0[u*4+2]=f0.z; v0[u*4+3]=f0.w;
                v1[u*4+0]=f1.x; v1[u*4+1]=f1.y; v1[u*4+2]=f1.z; v1[u*4+3]=f1.w;
            }
            float m0 = v0[0], m1 = v1[0];
            #pragma unroll
            for (int i = 1; i < 16; i++) { m0 = fmaxf(m0, v0[i]); m1 = fmaxf(m1, v1[i]); }
            m0 = fmaxf(m0, __shfl_xor_sync(0xffffffffu, m0, 1));
            m1 = fmaxf(m1, __shfl_xor_sync(0xffffffffu, m1, 1));
            m0 = fmaxf(m0, __shfl_xor_sync(0xffffffffu, m0, 2));
            m1 = fmaxf(m1, __shfl_xor_sync(0xffffffffu, m1, 2));
            float sm0 = 0.0f, sm1 = 0.0f;
            #pragma unroll
            for (int i = 0; i < 16; i++) {
                v0[i] = __expf(v0[i] - m0); sm0 += v0[i];
                v1[i] = __expf(v1[i] - m1); sm1 += v1[i];
            }
            sm0 += __shfl_xor_sync(0xffffffffu, sm0, 1);
            sm1 += __shfl_xor_sync(0xffffffffu, sm1, 1);
            sm0 += __shfl_xor_sync(0xffffffffu, sm0, 2);
            sm1 += __shfl_xor_sync(0xffffffffu, sm1, 2);
            const float i0 = 1.0f / sm0, i1 = 1.0f / sm1;
            // emit P A-fragments: row r, kt = p, pairs cp = 0..7
            const int mt = r >> 4, rin = r & 15, g2 = rin & 7, rh = rin >> 3;
            #pragma unroll
            for (int cp = 0; cp < 8; cp++) {
                const int lane2 = g2 * 4 + (cp & 3);
                const int slot  = rh + 2 * (cp >> 2);
                uint32_t hi, lo;
                split2(v0[cp * 2] * i0, v0[cp * 2 + 1] * i0, hi, lo);
                char* b0 = smc + paB[0] + (((mt * 4 + p) * 32 + lane2) << 4) + slot * 4;
                *reinterpret_cast<uint32_t*>(b0)        = hi;
                *reinterpret_cast<uint32_t*>(b0 + 8192) = lo;
                split2(v1[cp * 2] * i1, v1[cp * 2 + 1] * i1, hi, lo);
                char* b1 = smc + paB[1] + (((mt * 4 + p) * 32 + lane2) << 4) + slot * 4;
                *reinterpret_cast<uint32_t*>(b1)        = hi;
                *reinterpret_cast<uint32_t*>(b1 + 8192) = lo;
            }
        }
        __syncthreads();

        // ===== O = P V via HMMA (warp (mw, dh=nh)) -> OP pack =====
        {
            #pragma unroll
            for (int hh = 0; hh < 2; hh++) {
                uint4 PAh[4], PAl[4];
                #pragma unroll
                for (int kt = 0; kt < 4; kt++) {
                    const char* pb = smc + paB[hh] + (((mw * 4 + kt) * 32 + lane) << 4);
                    PAh[kt] = *reinterpret_cast<const uint4*>(pb);
                    PAl[kt] = *reinterpret_cast<const uint4*>(pb + 8192);
                }
                #pragma unroll
                for (int ntl = 0; ntl < 2; ntl++) {
                    const int n = nh * 16 + ntl * 8 + g;   // output d column
                    float oacc[4] = { 0.0f, 0.0f, 0.0f, 0.0f };
                    #pragma unroll
                    for (int kt = 0; kt < 4; kt++) {
                        const int k0 = kt * 16 + (lane & 3) * 2;
                        const float vk  = sV[hh][k0 * 34 + n];
                        const float vk1 = sV[hh][(k0 + 1) * 34 + n];
                        const float vk8 = sV[hh][(k0 + 8) * 34 + n];
                        const float vk9 = sV[hh][(k0 + 9) * 34 + n];
                        uint32_t hw0, lw0, hw1, lw1;
                        split2(vk,  vk1, hw0, lw0);
                        split2(vk8, vk9, hw1, lw1);
                        const uint2 Bh = make_uint2(hw0, hw1);
                        const uint2 Bl = make_uint2(lw0, lw1);
                        mma16816(oacc, PAh[kt], Bh);
                        mma16816(oacc, PAh[kt], Bl);
                        mma16816(oacc, PAl[kt], Bh);
                    }
                    // O D-frag maps in-lane to OP A-frag pack: kt = dh(nh), slot = rh + 2*ntl
                    uint32_t hi, lo;
                    char* base = smc + opB[hh] + (((mw * 2 + nh) * 32 + lane) << 4);
                    split2(oacc[0], oacc[1], hi, lo);
                    *reinterpret_cast<uint32_t*>(base + (0 + 2 * ntl) * 4)        = hi;
                    *reinterpret_cast<uint32_t*>(base + (0 + 2 * ntl) * 4 + 4096) = lo;
                    split2(oacc[2], oacc[3], hi, lo);
                    *reinterpret_cast<uint32_t*>(base + (1 + 2 * ntl) * 4)        = hi;
                    *reinterpret_cast<uint32_t*>(base + (1 + 2 * ntl) * 4 + 4096) = lo;
                }
            }
        }
        __syncthreads();

        // ===== GEMM2 (both heads): Y += O_h @ Wproj_h^T (reg accumulate) =====
        #pragma unroll
        for (int hh = 0; hh < 2; hh++) {
            const int h = h0 + hh;
            const uint2* w2h = gW2h + ((h * 32 + nh * 16) * 2) * 32 + lane;
            const uint2* w2l = gW2l + ((h * 32 + nh * 16) * 2) * 32 + lane;
            #pragma unroll
            for (int kt = 0; kt < 2; kt++) {
                const char* ab = smc + opB[hh] + (((mw * 2 + kt) * 32 + lane) << 4);
                const uint4 Ah = *reinterpret_cast<const uint4*>(ab);
                const uint4 Al = *reinterpret_cast<const uint4*>(ab + 4096);
                #pragma unroll
                for (int nt = 0; nt < 16; nt++) {
                    const uint2 Bh = __ldg(&w2h[(nt * 2 + kt) * 32]);
                    const uint2 Bl = __ldg(&w2l[(nt * 2 + kt) * 32]);
                    mma16816(acc2[nt], Ah, Bh);
                    mma16816(acc2[nt], Ah, Bl);
                    mma16816(acc2[nt], Al, Bh);
                }
            }
        }
        // no barrier: next pair's pack writes are ordered by >=2 intervening barriers
    } // head pairs

    // ---------------- epilogue: Y + b_proj -> global ----------------
    {
        const int c = (lane & 3) * 2;
        const int tok0 = mw * 16 + g, tok1 = tok0 + 8;
        float* g0 = out + row_gbase(win, tok0);
        float* g1 = out + row_gbase(win, tok1);
        #pragma unroll
        for (int nt = 0; nt < 16; nt++) {
            const int colb = (nh * 16 + nt) * 8 + c;
            const float b0 = sBiasP[colb], b1 = sBiasP[colb + 1];
            float2 v0 = make_float2(acc2[nt][0] + b0, acc2[nt][1] + b1);
            float2 v1 = make_float2(acc2[nt][2] + b0, acc2[nt][3] + b1);
            *reinterpret_cast<float2*>(g0 + colb) = v0;
            *reinterpret_cast<float2*>(g1 + colb) = v1;
        }
    }
}

extern "C" void kernel_launch(void* const* d_in, const int* in_sizes, int n_in,
                              void* d_out, int out_size)
{
    const float* x      = (const float*)d_in[0];
    const float* w_qkv  = (const float*)d_in[1];
    const float* b_qkv  = (const float*)d_in[2];
    const float* w_proj = (const float*)d_in[3];
    const float* b_proj = (const float*)d_in[4];
    float* out = (float*)d_out;
    (void)in_sizes; (void)n_in; (void)out_size;

    pack_w1_kernel<<<192, 256>>>(w_qkv);
    pack_w2_kernel<<<64, 256>>>(w_proj);

    cudaFuncSetAttribute(win_mhsa_mma_kernel,
                         cudaFuncAttributeMaxDynamicSharedMemorySize, SMEM_TOTAL);
    win_mhsa_mma_kernel<<<NWIN, 256, SMEM_TOTAL>>>(x, b_qkv, b_proj, out);
}

// round 17
// speedup vs baseline: 1.2288x; 1.0082x over previous
#include <cuda_runtime.h>
#include <cuda_bf16.h>
#include <cstdint>

// LocalAttention2D: windowed MHSA, fully tensorized GEMMs (mma.sync bf16 hi/lo
// split, 3-term, fp32 accum) including S=QK^T and O=PV. Softmax in fp32 SIMT.
// One window per CTA, 256 threads, heads in pairs (4 barriers/pair).
// Weights pre-packed as FUSED uint4 fragments {hi2,lo2} in gmem (1 LDG.128 each).

#define NWIN 4608

// ---- SMEM byte layout ----
#define XP_B      0        // X A-frag pack: [2 plane][4 mt][16 kt][32][16B] = 65536
#define OP0_B     65536    // O A-frag pack head0 (2 planes x 4096) = 8192
#define OP1_B     73728
#define QA0_B     81920    // Q A-frag pack: [2 plane][4 mt][2 kt][32][16B] = 8192
#define QA1_B     90112
#define KB0_B     98304    // K B-frag pack: [2 plane][8 nt][2 kt][32][8B] = 8192
#define KB1_B     106496
#define PA0_B     114688   // P A-frag pack: [2 plane][4 mt][4 kt][32][16B] = 16384
#define PA1_B     131072
#define SV0_B     147456   // V planar [64 tok][34 d] f32 = 8704
#define SV1_B     156160
#define SS0_B     164864   // S [64][68] f32 = 17408
#define SS1_B     182272
#define SBIASQ_B  199680   // 768 f32
#define SBIASP_B  202752   // 256 f32
#define SMEM_TOTAL 203776

// ---- global packed weights: fused B-fragments {hi.x,hi.y,lo.x,lo.y} ----
__device__ uint4 gW1f[8 * 12 * 16 * 32];
__device__ uint4 gW2f[8 * 32 * 2 * 32];

__device__ __forceinline__ void mma16816(float* d, const uint4 a, const uint2 b) {
    asm volatile(
        "mma.sync.aligned.m16n8k16.row.col.f32.bf16.bf16.f32 "
        "{%0,%1,%2,%3}, {%4,%5,%6,%7}, {%8,%9}, {%0,%1,%2,%3};\n"
        : "+f"(d[0]), "+f"(d[1]), "+f"(d[2]), "+f"(d[3])
        : "r"(a.x), "r"(a.y), "r"(a.z), "r"(a.w), "r"(b.x), "r"(b.y));
}

__device__ __forceinline__ void split2(float a, float b, uint32_t& hi, uint32_t& lo) {
    __nv_bfloat16 ha = __float2bfloat16(a), hb = __float2bfloat16(b);
    float ra = a - __bfloat162float(ha), rb = b - __bfloat162float(hb);
    __nv_bfloat16 la = __float2bfloat16(ra), lb = __float2bfloat16(rb);
    hi = (uint32_t)__bfloat16_as_ushort(ha) | ((uint32_t)__bfloat16_as_ushort(hb) << 16);
    lo = (uint32_t)__bfloat16_as_ushort(la) | ((uint32_t)__bfloat16_as_ushort(lb) << 16);
}

// ---------------- pre-pack kernels (fused uint4 variant of verified R8) ----------------
__global__ void pack_w1_kernel(const float* __restrict__ w_qkv) {
    const int gid = blockIdx.x * 256 + threadIdx.x;     // 0..49151
    const int lane = gid & 31;
    const int kt   = (gid >> 5) & 15;
    const int nt   = (gid >> 9) % 12;
    const int h    = (gid >> 9) / 12;
    const int c    = nt * 8 + (lane >> 2);
    const int grow = (c >> 5) * 256 + h * 32 + (c & 31);
    const int k0   = kt * 16 + (lane & 3) * 2;
    const float a0 = w_qkv[grow * 256 + k0],     a1 = w_qkv[grow * 256 + k0 + 1];
    const float b0 = w_qkv[grow * 256 + k0 + 8], b1 = w_qkv[grow * 256 + k0 + 9];
    uint32_t hx, lx, hy, ly;
    split2(a0, a1, hx, lx);
    split2(b0, b1, hy, ly);
    gW1f[gid] = make_uint4(hx, hy, lx, ly);
}

__global__ void pack_w2_kernel(const float* __restrict__ w_proj) {
    const int gid = blockIdx.x * 256 + threadIdx.x;     // 0..16383
    const int lane = gid & 31;
    const int kt   = (gid >> 5) & 1;
    const int nt   = (gid >> 6) & 31;
    const int h    = gid >> 11;
    const int n    = nt * 8 + (lane >> 2);
    const int k    = h * 32 + kt * 16 + (lane & 3) * 2;
    const float a0 = w_proj[n * 256 + k],     a1 = w_proj[n * 256 + k + 1];
    const float b0 = w_proj[n * 256 + k + 8], b1 = w_proj[n * 256 + k + 9];
    uint32_t hx, lx, hy, ly;
    split2(a0, a1, hx, lx);
    split2(b0, b1, hy, ly);
    gW2f[gid] = make_uint4(hx, hy, lx, ly);
}

__device__ __forceinline__ int row_gbase(int win, int tok) {
    const int b  = win / 576;
    const int wh = (win % 576) / 24;
    const int ww = win % 24;
    return ((b * 192 + wh * 8 + (tok >> 3)) * 192 + (ww * 8 + (tok & 7))) * 256;
}

__global__ __launch_bounds__(256, 1)
void win_mhsa_mma_kernel(const float* __restrict__ x,
                         const float* __restrict__ b_qkv,
                         const float* __restrict__ b_proj,
                         float* __restrict__ out)
{
    extern __shared__ char smc[];
    float* sV[2] = { (float*)(smc + SV0_B), (float*)(smc + SV1_B) };
    float* sS[2] = { (float*)(smc + SS0_B), (float*)(smc + SS1_B) };
    float* sBiasQ = (float*)(smc + SBIASQ_B);
    float* sBiasP = (float*)(smc + SBIASP_B);
    const int opB[2] = { OP0_B, OP1_B };
    const int qaB[2] = { QA0_B, QA1_B };
    const int kbB[2] = { KB0_B, KB1_B };
    const int paB[2] = { PA0_B, PA1_B };

    const int tid  = threadIdx.x;
    const int wid  = tid >> 5;
    const int lane = tid & 31;
    const int win  = blockIdx.x;
    const float QSCALE = 0.17677669529663689f;   // 32^-0.5

    sBiasP[tid] = __ldg(&b_proj[tid]);
    sBiasQ[tid] = __ldg(&b_qkv[tid]);
    sBiasQ[tid + 256] = __ldg(&b_qkv[tid + 256]);
    sBiasQ[tid + 512] = __ldg(&b_qkv[tid + 512]);

    // ---------------- X window -> A-fragment pack (hi/lo bf16) ----------------
    {
        const int row = tid >> 2, p = tid & 3;
        const float4* gx = reinterpret_cast<const float4*>(x + row_gbase(win, row));
        const int mt = row >> 4, rin = row & 15, g = rin & 7, rh = rin >> 3;
        #pragma unroll
        for (int u = 0; u < 16; u++) {
            const int k4 = p * 16 + u;
            const float4 v = __ldg(&gx[k4]);
            const int ktile = k4 >> 2;
            const int cpair = (k4 & 3) * 2;
            const float e[4] = { v.x, v.y, v.z, v.w };
            #pragma unroll
            for (int pr = 0; pr < 2; pr++) {
                const int cp = cpair + pr, c8 = cp >> 2, cc = cp & 3;
                const int laneX = g * 4 + cc, slot = rh + 2 * c8;
                uint32_t hi, lo;
                split2(e[pr * 2], e[pr * 2 + 1], hi, lo);
                char* base = smc + XP_B + (((mt * 16 + ktile) * 32 + laneX) << 4) + slot * 4;
                *reinterpret_cast<uint32_t*>(base)         = hi;
                *reinterpret_cast<uint32_t*>(base + 32768) = lo;
            }
        }
    }
    __syncthreads();

    const int mw = wid & 3;      // M-tile (16 tokens)
    const int nh = wid >> 2;     // N-half
    const int g  = lane >> 2;    // row-in-8 group

    float acc2[16][4];
    #pragma unroll
    for (int i = 0; i < 16; i++)
        #pragma unroll
        for (int j = 0; j < 4; j++) acc2[i][j] = 0.0f;

    for (int hp = 0; hp < 4; hp++) {
        const int h0 = hp * 2, h1 = h0 + 1;

        // ===== GEMM1 (both heads): QKV[64,96] = X @ Wh^T =====
        float acc1[2][6][4];
        #pragma unroll
        for (int hh = 0; hh < 2; hh++)
            #pragma unroll
            for (int i = 0; i < 6; i++)
                #pragma unroll
                for (int j = 0; j < 4; j++) acc1[hh][i][j] = 0.0f;
        {
            const uint4* w1f0 = gW1f + ((h0 * 12 + nh * 6) * 16) * 32 + lane;
            const uint4* w1f1 = gW1f + ((h1 * 12 + nh * 6) * 16) * 32 + lane;
            #pragma unroll 4
            for (int kt = 0; kt < 16; kt++) {
                const char* ab = smc + XP_B + (((mw * 16 + kt) * 32 + lane) << 4);
                const uint4 Ah = *reinterpret_cast<const uint4*>(ab);
                const uint4 Al = *reinterpret_cast<const uint4*>(ab + 32768);
                #pragma unroll
                for (int nt = 0; nt < 6; nt++) {
                    const uint4 W0 = __ldg(&w1f0[(nt * 16 + kt) * 32]);
                    const uint4 W1 = __ldg(&w1f1[(nt * 16 + kt) * 32]);
                    const uint2 Bh0 = make_uint2(W0.x, W0.y), Bl0 = make_uint2(W0.z, W0.w);
                    const uint2 Bh1 = make_uint2(W1.x, W1.y), Bl1 = make_uint2(W1.z, W1.w);
                    mma16816(acc1[0][nt], Ah, Bh0);
                    mma16816(acc1[1][nt], Ah, Bh1);
                    mma16816(acc1[0][nt], Ah, Bl0);
                    mma16816(acc1[1][nt], Ah, Bl1);
                    mma16816(acc1[0][nt], Al, Bh0);
                    mma16816(acc1[1][nt], Al, Bh1);
                }
            }
        }
        // scatter QKV (+bias) into fragment packs (Q: A-frag, K: B-frag, V: planar)
        {
            #pragma unroll
            for (int hh = 0; hh < 2; hh++) {
                const int h = h0 + hh;
                #pragma unroll
                for (int nt = 0; nt < 6; nt++) {
                    const int q = nh * 6 + nt;            // 0..11 col-octet
                    const int colb = q * 8 + (lane & 3) * 2;
                    float v0 = acc1[hh][nt][0] + sBiasQ[((colb    ) >> 5) * 256 + h * 32 + ((colb    ) & 31)];
                    float v1 = acc1[hh][nt][1] + sBiasQ[((colb + 1) >> 5) * 256 + h * 32 + ((colb + 1) & 31)];
                    float v2 = acc1[hh][nt][2] + sBiasQ[((colb    ) >> 5) * 256 + h * 32 + ((colb    ) & 31)];
                    float v3 = acc1[hh][nt][3] + sBiasQ[((colb + 1) >> 5) * 256 + h * 32 + ((colb + 1) & 31)];
                    if (q < 4) {
                        // Q: scale then A-frag pack
                        v0 *= QSCALE; v1 *= QSCALE; v2 *= QSCALE; v3 *= QSCALE;
                        const int kt = q >> 1, c8 = q & 1;
                        uint32_t h01, l01, h23, l23;
                        split2(v0, v1, h01, l01);
                        split2(v2, v3, h23, l23);
                        char* base = smc + qaB[hh] + (((mw * 2 + kt) * 32 + lane) << 4);
                        *reinterpret_cast<uint32_t*>(base + (0 + 2 * c8) * 4)        = h01;
                        *reinterpret_cast<uint32_t*>(base + (1 + 2 * c8) * 4)        = h23;
                        *reinterpret_cast<uint32_t*>(base + (0 + 2 * c8) * 4 + 4096) = l01;
                        *reinterpret_cast<uint32_t*>(base + (1 + 2 * c8) * 4 + 4096) = l23;
                    } else if (q < 8) {
                        // K: B-frag pack. rows t=mw*16+g -> ntj=mw*2 ; t+8 -> ntj=mw*2+1
                        const int kt = (q - 4) >> 1, w = (q - 4) & 1;
                        uint32_t hi, lo;
                        split2(v0, v1, hi, lo);
                        char* b0 = smc + kbB[hh] + ((((mw * 2 + 0) * 2 + kt) * 32 + lane) << 3) + w * 4;
                        *reinterpret_cast<uint32_t*>(b0)        = hi;
                        *reinterpret_cast<uint32_t*>(b0 + 4096) = lo;
                        split2(v2, v3, hi, lo);
                        char* b1 = smc + kbB[hh] + ((((mw * 2 + 1) * 2 + kt) * 32 + lane) << 3) + w * 4;
                        *reinterpret_cast<uint32_t*>(b1)        = hi;
                        *reinterpret_cast<uint32_t*>(b1 + 4096) = lo;
                    } else {
                        // V: planar [tok][34]
                        const int d = (q - 8) * 8 + (lane & 3) * 2;
                        const int t = mw * 16 + g;
                        *reinterpret_cast<float2*>(&sV[hh][t * 34 + d])       = make_float2(v0, v1);
                        *reinterpret_cast<float2*>(&sV[hh][(t + 8) * 34 + d]) = make_float2(v2, v3);
                    }
                }
            }
        }
        __syncthreads();

        // ===== S = Q K^T via HMMA (warp (mw, jh=nh): rows mw*16.., cols nh*32..) =====
        {
            #pragma unroll
            for (int hh = 0; hh < 2; hh++) {
                uint4 Ah[2], Al[2];
                #pragma unroll
                for (int kt = 0; kt < 2; kt++) {
                    const char* qb = smc + qaB[hh] + (((mw * 2 + kt) * 32 + lane) << 4);
                    Ah[kt] = *reinterpret_cast<const uint4*>(qb);
                    Al[kt] = *reinterpret_cast<const uint4*>(qb + 4096);
                }
                #pragma unroll
                for (int ntl = 0; ntl < 4; ntl++) {
                    const int ntj = nh * 4 + ntl;
                    float sacc[4] = { 0.0f, 0.0f, 0.0f, 0.0f };
                    #pragma unroll
                    for (int kt = 0; kt < 2; kt++) {
                        const char* kb = smc + kbB[hh] + (((ntj * 2 + kt) * 32 + lane) << 3);
                        const uint2 Bh = *reinterpret_cast<const uint2*>(kb);
                        const uint2 Bl = *reinterpret_cast<const uint2*>(kb + 4096);
                        mma16816(sacc, Ah[kt], Bh);
                        mma16816(sacc, Ah[kt], Bl);
                        mma16816(sacc, Al[kt], Bh);
                    }
                    const int t = mw * 16 + g;
                    const int j = ntj * 8 + (lane & 3) * 2;
                    *reinterpret_cast<float2*>(&sS[hh][t * 68 + j])       = make_float2(sacc[0], sacc[1]);
                    *reinterpret_cast<float2*>(&sS[hh][(t + 8) * 68 + j]) = make_float2(sacc[2], sacc[3]);
                }
            }
        }
        __syncthreads();

        // ===== softmax rows (both heads) -> P A-frag pack =====
        {
            const int r = tid >> 2, p = tid & 3;
            float v0[16], v1[16];
            const float* row0 = &sS[0][r * 68 + p * 16];
            const float* row1 = &sS[1][r * 68 + p * 16];
            #pragma unroll
            for (int u = 0; u < 4; u++) {
                const float4 f0 = *reinterpret_cast<const float4*>(row0 + u * 4);
                const float4 f1 = *reinterpret_cast<const float4*>(row1 + u * 4);
                v0[u*4+0]=f0.x; v0[u*4+1]=f0.y; v0[u*4+2]=f0.z; v0[u*4+3]=f0.w;
                v1[u*4+0]=f1.x; v1[u*4+1]=f1.y; v1[u*4+2]=f1.z; v1[u*4+3]=f1.w;
            }
            float m0 = v0[0], m1 = v1[0];
            #pragma unroll
            for (int i = 1; i < 16; i++) { m0 = fmaxf(m0, v0[i]); m1 = fmaxf(m1, v1[i]); }
            m0 = fmaxf(m0, __shfl_xor_sync(0xffffffffu, m0, 1));
            m1 = fmaxf(m1, __shfl_xor_sync(0xffffffffu, m1, 1));
            m0 = fmaxf(m0, __shfl_xor_sync(0xffffffffu, m0, 2));
            m1 = fmaxf(m1, __shfl_xor_sync(0xffffffffu, m1, 2));
            float sm0 = 0.0f, sm1 = 0.0f;
            #pragma unroll
            for (int i = 0; i < 16; i++) {
                v0[i] = __expf(v0[i] - m0); sm0 += v0[i];
                v1[i] = __expf(v1[i] - m1); sm1 += v1[i];
            }
            sm0 += __shfl_xor_sync(0xffffffffu, sm0, 1);
            sm1 += __shfl_xor_sync(0xffffffffu, sm1, 1);
            sm0 += __shfl_xor_sync(0xffffffffu, sm0, 2);
            sm1 += __shfl_xor_sync(0xffffffffu, sm1, 2);
            const float i0 = 1.0f / sm0, i1 = 1.0f / sm1;
            // emit P A-fragments: row r, kt = p, pairs cp = 0..7
            const int mt = r >> 4, rin = r & 15, g2 = rin & 7, rh = rin >> 3;
            #pragma unroll
            for (int cp = 0; cp < 8; cp++) {
                const int lane2 = g2 * 4 + (cp & 3);
                const int slot  = rh + 2 * (cp >> 2);
                uint32_t hi, lo;
                split2(v0[cp * 2] * i0, v0[cp * 2 + 1] * i0, hi, lo);
                char* b0 = smc + paB[0] + (((mt * 4 + p) * 32 + lane2) << 4) + slot * 4;
                *reinterpret_cast<uint32_t*>(b0)        = hi;
                *reinterpret_cast<uint32_t*>(b0 + 8192) = lo;
                split2(v1[cp * 2] * i1, v1[cp * 2 + 1] * i1, hi, lo);
                char* b1 = smc + paB[1] + (((mt * 4 + p) * 32 + lane2) << 4) + slot * 4;
                *reinterpret_cast<uint32_t*>(b1)        = hi;
                *reinterpret_cast<uint32_t*>(b1 + 8192) = lo;
            }
        }
        __syncthreads();

        // ===== O = P V via HMMA (warp (mw, dh=nh)) -> OP pack =====
        {
            #pragma unroll
            for (int hh = 0; hh < 2; hh++) {
                uint4 PAh[4], PAl[4];
                #pragma unroll
                for (int kt = 0; kt < 4; kt++) {
                    const char* pb = smc + paB[hh] + (((mw * 4 + kt) * 32 + lane) << 4);
                    PAh[kt] = *reinterpret_cast<const uint4*>(pb);
                    PAl[kt] = *reinterpret_cast<const uint4*>(pb + 8192);
                }
                #pragma unroll
                for (int ntl = 0; ntl < 2; ntl++) {
                    const int n = nh * 16 + ntl * 8 + g;   // output d column
                    float oacc[4] = { 0.0f, 0.0f, 0.0f, 0.0f };
                    #pragma unroll
                    for (int kt = 0; kt < 4; kt++) {
                        const int k0 = kt * 16 + (lane & 3) * 2;
                        const float vk  = sV[hh][k0 * 34 + n];
                        const float vk1 = sV[hh][(k0 + 1) * 34 + n];
                        const float vk8 = sV[hh][(k0 + 8) * 34 + n];
                        const float vk9 = sV[hh][(k0 + 9) * 34 + n];
                        uint32_t hw0, lw0, hw1, lw1;
                        split2(vk,  vk1, hw0, lw0);
                        split2(vk8, vk9, hw1, lw1);
                        const uint2 Bh = make_uint2(hw0, hw1);
                        const uint2 Bl = make_uint2(lw0, lw1);
                        mma16816(oacc, PAh[kt], Bh);
                        mma16816(oacc, PAh[kt], Bl);
                        mma16816(oacc, PAl[kt], Bh);
                    }
                    // O D-frag maps in-lane to OP A-frag pack: kt = dh(nh), slot = rh + 2*ntl
                    uint32_t hi, lo;
                    char* base = smc + opB[hh] + (((mw * 2 + nh) * 32 + lane) << 4);
                    split2(oacc[0], oacc[1], hi, lo);
                    *reinterpret_cast<uint32_t*>(base + (0 + 2 * ntl) * 4)        = hi;
                    *reinterpret_cast<uint32_t*>(base + (0 + 2 * ntl) * 4 + 4096) = lo;
                    split2(oacc[2], oacc[3], hi, lo);
                    *reinterpret_cast<uint32_t*>(base + (1 + 2 * ntl) * 4)        = hi;
                    *reinterpret_cast<uint32_t*>(base + (1 + 2 * ntl) * 4 + 4096) = lo;
                }
            }
        }
        __syncthreads();

        // ===== GEMM2 (both heads): Y += O_h @ Wproj_h^T (reg accumulate) =====
        #pragma unroll
        for (int hh = 0; hh < 2; hh++) {
            const int h = h0 + hh;
            const uint4* w2f = gW2f + ((h * 32 + nh * 16) * 2) * 32 + lane;
            #pragma unroll
            for (int kt = 0; kt < 2; kt++) {
                const char* ab = smc + opB[hh] + (((mw * 2 + kt) * 32 + lane) << 4);
                const uint4 Ah = *reinterpret_cast<const uint4*>(ab);
                const uint4 Al = *reinterpret_cast<const uint4*>(ab + 4096);
                #pragma unroll
                for (int nt = 0; nt < 16; nt++) {
                    const uint4 W = __ldg(&w2f[(nt * 2 + kt) * 32]);
                    const uint2 Bh = make_uint2(W.x, W.y), Bl = make_uint2(W.z, W.w);
                    mma16816(acc2[nt], Ah, Bh);
                    mma16816(acc2[nt], Ah, Bl);
                    mma16816(acc2[nt], Al, Bh);
                }
            }
        }
        // no barrier: next pair's pack writes are ordered by >=2 intervening barriers
    } // head pairs

    // ---------------- epilogue: Y + b_proj -> global ----------------
    {
        const int c = (lane & 3) * 2;
        const int tok0 = mw * 16 + g, tok1 = tok0 + 8;
        float* g0 = out + row_gbase(win, tok0);
        float* g1 = out + row_gbase(win, tok1);
        #pragma unroll
        for (int nt = 0; nt < 16; nt++) {
            const int colb = (nh * 16 + nt) * 8 + c;
            const float b0 = sBiasP[colb], b1 = sBiasP[colb + 1];
            float2 v0 = make_float2(acc2[nt][0] + b0, acc2[nt][1] + b1);
            float2 v1 = make_float2(acc2[nt][2] + b0, acc2[nt][3] + b1);
            *reinterpret_cast<float2*>(g0 + colb) = v0;
            *reinterpret_cast<float2*>(g1 + colb) = v1;
        }
    }
}

extern "C" void kernel_launch(void* const* d_in, const int* in_sizes, int n_in,
                              void* d_out, int out_size)
{
    const float* x      = (const float*)d_in[0];
    const float* w_qkv  = (const float*)d_in[1];
    const float* b_qkv  = (const float*)d_in[2];
    const float* w_proj = (const float*)d_in[3];
    const float* b_proj = (const float*)d_in[4];
    float* out = (float*)d_out;
    (void)in_sizes; (void)n_in; (void)out_size;

    pack_w1_kernel<<<192, 256>>>(w_qkv);
    pack_w2_kernel<<<64, 256>>>(w_proj);

    cudaFuncSetAttribute(win_mhsa_mma_kernel,
                         cudaFuncAttributeMaxDynamicSharedMemorySize, SMEM_TOTAL);
    win_mhsa_mma_kernel<<<NWIN, 256, SMEM_TOTAL>>>(x, b_qkv, b_proj, out);
}